// round 1
// baseline (speedup 1.0000x reference)
#include <cuda_runtime.h>
#include <math.h>

// ---------------------------------------------------------------------------
// Problem constants
// ---------------------------------------------------------------------------
#define Bn_TOK   100352      // B*D*H*W = 8*4*56*56 = total tokens = 1024 windows * 98
#define NWIN     1024        // B * NW = 8 * 128
#define NTOK     98          // tokens per window
#define CDIM     128
#define HEADS    4
#define HDIM     32
#define SCALE_Q  0.17677669529663687f   // 32^-0.5
#define LN_EPS   1e-5f

// ---------------------------------------------------------------------------
// Scratch (static device globals; allocation-free per harness rules)
// ---------------------------------------------------------------------------
__device__ float g_xw  [(long long)Bn_TOK * 128];   // LN1 + shift + window-partitioned
__device__ float g_qkv [(long long)Bn_TOK * 384];
__device__ float g_att [(long long)Bn_TOK * 128];   // attention output (window layout)
__device__ float g_x1  [(long long)Bn_TOK * 128];   // shortcut + proj (token layout)
__device__ float g_h2  [(long long)Bn_TOK * 128];   // LN2 output
__device__ float g_hid [(long long)Bn_TOK * 512];   // fc1+gelu

// ---------------------------------------------------------------------------
// Window-token <-> source-token mapping (shift = (1,3,3), window (2,7,7))
// row = win*98 + n  ->  original-layout token index
// ---------------------------------------------------------------------------
__device__ __forceinline__ int map_winrow_to_token(int row)
{
    int win = row / 98, n = row - win * 98;
    int b    = win >> 7;          // /128
    int winS = win & 127;
    int wd = winS >> 6, wh = (winS >> 3) & 7, ww = winS & 7;
    int td = n / 49, rem = n - td * 49, th = rem / 7, tw = rem - th * 7;
    int d = wd * 2 + td;
    int h = wh * 7 + th;
    int w = ww * 7 + tw;
    int ds = (d + 1) & 3;
    int hs = h + 3; if (hs >= 56) hs -= 56;
    int ws = w + 3; if (ws >= 56) ws -= 56;
    return ((b * 4 + ds) * 56 + hs) * 56 + ws;
}

// ---------------------------------------------------------------------------
// LayerNorm (one block = one token, 128 threads).
// gather != 0: input read from shifted/windowed source position (LN1 path)
// ---------------------------------------------------------------------------
__global__ void ln_kernel(const float* __restrict__ in,
                          const float* __restrict__ gam,
                          const float* __restrict__ bet,
                          float* __restrict__ out, int gather)
{
    int row = blockIdx.x;
    int tid = threadIdx.x;
    int src = gather ? map_winrow_to_token(row) : row;
    float v = in[(long long)src * 128 + tid];

    float s = v, s2 = v * v;
    #pragma unroll
    for (int o = 16; o; o >>= 1) {
        s  += __shfl_down_sync(0xffffffffu, s,  o);
        s2 += __shfl_down_sync(0xffffffffu, s2, o);
    }
    __shared__ float red[8];
    __shared__ float s_mu, s_rs;
    int wid = tid >> 5;
    if ((tid & 31) == 0) { red[wid] = s; red[4 + wid] = s2; }
    __syncthreads();
    if (tid == 0) {
        float su = red[0] + red[1] + red[2] + red[3];
        float sq = red[4] + red[5] + red[6] + red[7];
        float mu  = su * (1.f / 128.f);
        float var = sq * (1.f / 128.f) - mu * mu;
        s_mu = mu;
        s_rs = rsqrtf(var + LN_EPS);
    }
    __syncthreads();
    out[(long long)row * 128 + tid] = (v - s_mu) * s_rs * gam[tid] + bet[tid];
}

// ---------------------------------------------------------------------------
// Fused attention: one block per (window, head). Everything in smem.
// qkv layout per window-token row: [q(128) | k(128) | v(128)], head slice *32.
// ---------------------------------------------------------------------------
#define ATTN_SMEM ((3 * 3136 + 98 * 100) * 4)   // 76832 bytes dynamic

__global__ void attn_kernel(const float* __restrict__ qkv,
                            const float* __restrict__ rpb,
                            float* __restrict__ out)
{
    int blk  = blockIdx.x;
    int win  = blk >> 2;
    int head = blk & 3;
    int tid  = threadIdx.x;

    extern __shared__ float sm[];
    float* qs = sm;                 // 98*32
    float* ks = sm + 3136;
    float* vs = sm + 6272;
    float* ss = sm + 9408;          // 98 rows * 100 (padded)
    __shared__ int lab[98];

    int winS = win & 127;
    int wd = winS >> 6, wh = (winS >> 3) & 7, ww = winS & 7;
    if (tid < 98) {
        int td = tid / 49, rem = tid - td * 49, th = rem / 7, tw = rem - th * 7;
        int d = wd * 2 + td, h = wh * 7 + th, w = ww * 7 + tw;
        int dr = d < 2 ? 0 : (d < 3 ? 1 : 2);
        int hr = h < 49 ? 0 : (h < 53 ? 1 : 2);
        int wr = w < 49 ? 0 : (w < 53 ? 1 : 2);
        lab[tid] = dr * 9 + hr * 3 + wr;
    }

    const float* base = qkv + (long long)win * 98 * 384 + head * 32;
    for (int idx = tid; idx < 3136; idx += 128) {
        int i = idx >> 5, c = idx & 31;
        const float* r = base + i * 384 + c;
        qs[idx] = r[0] * SCALE_Q;
        ks[idx] = r[128];
        vs[idx] = r[256];
    }
    __syncthreads();

    // S = qk^T + rel-pos bias + shift mask
    for (int e = tid; e < 9604; e += 128) {
        int i = e / 98, j = e - i * 98;
        float acc = 0.f;
        #pragma unroll
        for (int c = 0; c < 32; c++) acc += qs[i * 32 + c] * ks[j * 32 + c];
        int di = i / 49, ri = i - di * 49, hi = ri / 7, wi = ri - hi * 7;
        int dj = j / 49, rj = j - dj * 49, hj = rj / 7, wj = rj - hj * 7;
        int rel = (di - dj + 1) * 169 + (hi - hj + 6) * 13 + (wi - wj + 6);
        float bias = rpb[rel * 4 + head];
        float msk  = (lab[i] == lab[j]) ? 0.f : -100.f;
        ss[i * 100 + j] = acc + bias + msk;
    }
    __syncthreads();

    // row softmax (one thread per row)
    if (tid < 98) {
        float* r = ss + tid * 100;
        float mx = -1e30f;
        #pragma unroll 7
        for (int j = 0; j < 98; j++) mx = fmaxf(mx, r[j]);
        float sum = 0.f;
        #pragma unroll 7
        for (int j = 0; j < 98; j++) { float e = __expf(r[j] - mx); r[j] = e; sum += e; }
        float inv = 1.f / sum;
        #pragma unroll 7
        for (int j = 0; j < 98; j++) r[j] *= inv;
    }
    __syncthreads();

    // out = P @ V
    float* obase = out + (long long)win * 98 * 128 + head * 32;
    for (int idx = tid; idx < 3136; idx += 128) {
        int i = idx >> 5, c = idx & 31;
        float acc = 0.f;
        #pragma unroll 7
        for (int j = 0; j < 98; j++) acc += ss[i * 100 + j] * vs[j * 32 + c];
        obase[i * 128 + c] = acc;
    }
}

// ---------------------------------------------------------------------------
// Tiled fp32 GEMM: C = act(A[M,K] @ B[K,N] + bias) (+ epilogue variants)
// BM=BN=128, BK=16, 256 threads, 8x8 per-thread microtile.
// Requires M%128==0, N%128==0, K%16==0.
// EPI 0: C[row,col] = v
// EPI 1: dest = window-reverse+unshift(row); C[dest,col] = res[dest,col] + v  (N==128)
// EPI 2: C[row,col] = res[row,col] + v
// ACT 1: exact GELU
// ---------------------------------------------------------------------------
template<int ACT, int EPI>
__global__ void __launch_bounds__(256)
gemm_kernel(const float* __restrict__ A, const float* __restrict__ B,
            const float* __restrict__ bias, float* __restrict__ C,
            const float* __restrict__ res, int M, int N, int K)
{
    __shared__ float As[16][132];
    __shared__ float Bs[16][132];

    int tid = threadIdx.x;
    int tx = tid & 15, ty = tid >> 4;
    int m0 = blockIdx.y * 128;
    int n0 = blockIdx.x * 128;

    float acc[8][8];
    #pragma unroll
    for (int i = 0; i < 8; i++)
        #pragma unroll
        for (int j = 0; j < 8; j++) acc[i][j] = 0.f;

    int arow0 = tid >> 2;      // [0,64)
    int akq   = tid & 3;
    int brow0 = tid >> 5;      // [0,8)
    int bnq   = tid & 31;

    for (int k0 = 0; k0 < K; k0 += 16) {
        #pragma unroll
        for (int r = 0; r < 2; r++) {
            int row = arow0 + r * 64;
            float4 av = *(const float4*)(A + (long long)(m0 + row) * K + k0 + akq * 4);
            As[akq * 4 + 0][row] = av.x;
            As[akq * 4 + 1][row] = av.y;
            As[akq * 4 + 2][row] = av.z;
            As[akq * 4 + 3][row] = av.w;
        }
        #pragma unroll
        for (int r = 0; r < 2; r++) {
            int row = brow0 + r * 8;
            float4 bv = *(const float4*)(B + (long long)(k0 + row) * N + n0 + bnq * 4);
            *(float4*)&Bs[row][bnq * 4] = bv;
        }
        __syncthreads();
        #pragma unroll
        for (int kk = 0; kk < 16; kk++) {
            float a[8], b[8];
            *(float4*)(a)     = *(float4*)&As[kk][ty * 8];
            *(float4*)(a + 4) = *(float4*)&As[kk][ty * 8 + 4];
            *(float4*)(b)     = *(float4*)&Bs[kk][tx * 8];
            *(float4*)(b + 4) = *(float4*)&Bs[kk][tx * 8 + 4];
            #pragma unroll
            for (int i = 0; i < 8; i++)
                #pragma unroll
                for (int j = 0; j < 8; j++)
                    acc[i][j] += a[i] * b[j];
        }
        __syncthreads();
    }

    #pragma unroll
    for (int i = 0; i < 8; i++) {
        int row = m0 + ty * 8 + i;
        long long dest = row;
        if (EPI == 1) dest = map_winrow_to_token(row);
        #pragma unroll
        for (int j = 0; j < 8; j++) {
            int col = n0 + tx * 8 + j;
            float v = acc[i][j] + bias[col];
            if (ACT == 1) v = 0.5f * v * (1.f + erff(v * 0.70710678118654752f));
            if (EPI == 0)
                C[(long long)row * N + col] = v;
            else if (EPI == 1)
                C[dest * 128 + col] = res[dest * 128 + col] + v;
            else
                C[(long long)row * N + col] = res[(long long)row * N + col] + v;
        }
    }
}

// ---------------------------------------------------------------------------
// launch
// ---------------------------------------------------------------------------
extern "C" void kernel_launch(void* const* d_in, const int* in_sizes, int n_in,
                              void* d_out, int out_size)
{
    const float* x       = (const float*)d_in[0];
    const float* norm1_g = (const float*)d_in[1];
    const float* norm1_b = (const float*)d_in[2];
    const float* qkv_w   = (const float*)d_in[3];
    const float* qkv_b   = (const float*)d_in[4];
    const float* rpb     = (const float*)d_in[5];
    const float* proj_w  = (const float*)d_in[6];
    const float* proj_b  = (const float*)d_in[7];
    const float* norm2_g = (const float*)d_in[8];
    const float* norm2_b = (const float*)d_in[9];
    const float* fc1_w   = (const float*)d_in[10];
    const float* fc1_b   = (const float*)d_in[11];
    const float* fc2_w   = (const float*)d_in[12];
    const float* fc2_b   = (const float*)d_in[13];
    float* out = (float*)d_out;

    float *xw, *qkv, *att, *x1, *h2, *hid;
    cudaGetSymbolAddress((void**)&xw,  g_xw);
    cudaGetSymbolAddress((void**)&qkv, g_qkv);
    cudaGetSymbolAddress((void**)&att, g_att);
    cudaGetSymbolAddress((void**)&x1,  g_x1);
    cudaGetSymbolAddress((void**)&h2,  g_h2);
    cudaGetSymbolAddress((void**)&hid, g_hid);

    cudaFuncSetAttribute(attn_kernel, cudaFuncAttributeMaxDynamicSharedMemorySize, ATTN_SMEM);

    // 1) LN1 + cyclic shift + window partition
    ln_kernel<<<Bn_TOK, 128>>>(x, norm1_g, norm1_b, xw, 1);

    // 2) QKV projection
    gemm_kernel<0, 0><<<dim3(3, Bn_TOK / 128), 256>>>(xw, qkv_w, qkv_b, qkv, nullptr,
                                                      Bn_TOK, 384, 128);

    // 3) windowed attention (bias + mask + softmax + PV)
    attn_kernel<<<NWIN * HEADS, 128, ATTN_SMEM>>>(qkv, rpb, att);

    // 4) output projection + window reverse + unshift + shortcut residual
    gemm_kernel<0, 1><<<dim3(1, Bn_TOK / 128), 256>>>(att, proj_w, proj_b, x1, x,
                                                      Bn_TOK, 128, 128);

    // 5) LN2
    ln_kernel<<<Bn_TOK, 128>>>(x1, norm2_g, norm2_b, h2, 0);

    // 6) fc1 + GELU
    gemm_kernel<1, 0><<<dim3(4, Bn_TOK / 128), 256>>>(h2, fc1_w, fc1_b, hid, nullptr,
                                                      Bn_TOK, 512, 128);

    // 7) fc2 + residual -> final output
    gemm_kernel<0, 2><<<dim3(1, Bn_TOK / 128), 256>>>(hid, fc2_w, fc2_b, out, x1,
                                                      Bn_TOK, 128, 512);
}

// round 6
// speedup vs baseline: 1.4447x; 1.4447x over previous
#include <cuda_runtime.h>
#include <math.h>
#include <stdint.h>

// ---------------------------------------------------------------------------
// Problem constants
// ---------------------------------------------------------------------------
#define Bn_TOK   100352      // 8*4*56*56 = 1024 windows * 98
#define NWIN     1024
#define NTOK     98
#define SCALE_Q  0.17677669529663687f   // 32^-0.5
#define LN_EPS   1e-5f

// ---------------------------------------------------------------------------
// Scratch
// ---------------------------------------------------------------------------
__device__ float g_xw  [(long long)Bn_TOK * 128];
__device__ float g_qkv [(long long)Bn_TOK * 384];
__device__ float g_att [(long long)Bn_TOK * 128];
__device__ float g_x1  [(long long)Bn_TOK * 128];
__device__ float g_h2  [(long long)Bn_TOK * 128];
__device__ float g_hid [(long long)Bn_TOK * 512];

// ---------------------------------------------------------------------------
// window-row -> original token index (shift (1,3,3), window (2,7,7))
// ---------------------------------------------------------------------------
__device__ __forceinline__ int map_winrow_to_token(int row)
{
    int win = row / 98, n = row - win * 98;
    int b    = win >> 7;
    int winS = win & 127;
    int wd = winS >> 6, wh = (winS >> 3) & 7, ww = winS & 7;
    int td = n / 49, rem = n - td * 49, th = rem / 7, tw = rem - th * 7;
    int d = wd * 2 + td;
    int h = wh * 7 + th;
    int w = ww * 7 + tw;
    int ds = (d + 1) & 3;
    int hs = h + 3; if (hs >= 56) hs -= 56;
    int ws = w + 3; if (ws >= 56) ws -= 56;
    return ((b * 4 + ds) * 56 + hs) * 56 + ws;
}

// ---------------------------------------------------------------------------
// LayerNorm: one block per token, 128 threads
// ---------------------------------------------------------------------------
__global__ void ln_kernel(const float* __restrict__ in,
                          const float* __restrict__ gam,
                          const float* __restrict__ bet,
                          float* __restrict__ out, int gather)
{
    int row = blockIdx.x;
    int tid = threadIdx.x;
    int src = gather ? map_winrow_to_token(row) : row;
    float v = in[(long long)src * 128 + tid];

    float s = v, s2 = v * v;
    #pragma unroll
    for (int o = 16; o; o >>= 1) {
        s  += __shfl_down_sync(0xffffffffu, s,  o);
        s2 += __shfl_down_sync(0xffffffffu, s2, o);
    }
    __shared__ float red[8];
    __shared__ float s_mu, s_rs;
    int wid = tid >> 5;
    if ((tid & 31) == 0) { red[wid] = s; red[4 + wid] = s2; }
    __syncthreads();
    if (tid == 0) {
        float su = red[0] + red[1] + red[2] + red[3];
        float sq = red[4] + red[5] + red[6] + red[7];
        float mu  = su * (1.f / 128.f);
        float var = sq * (1.f / 128.f) - mu * mu;
        s_mu = mu;
        s_rs = rsqrtf(var + LN_EPS);
    }
    __syncthreads();
    out[(long long)row * 128 + tid] = (v - s_mu) * s_rs * gam[tid] + bet[tid];
}

// ---------------------------------------------------------------------------
// Fused windowed attention, 256 threads per (window, head) block.
// ---------------------------------------------------------------------------
#define ATTN_SMEM ((3 * 3136 + 98 * 100) * 4)   // 76832 B dynamic

__global__ void __launch_bounds__(256)
attn_kernel(const float* __restrict__ qkv,
            const float* __restrict__ rpb,
            float* __restrict__ out)
{
    int blk  = blockIdx.x;
    int win  = blk >> 2;
    int head = blk & 3;
    int tid  = threadIdx.x;

    extern __shared__ float sm[];
    float* qs = sm;                 // 98*32
    float* ks = sm + 3136;
    float* vs = sm + 6272;
    float* ss = sm + 9408;          // 98 * 100 (padded)
    __shared__ int lab[98];

    int winS = win & 127;
    int wd = winS >> 6, wh = (winS >> 3) & 7, ww = winS & 7;
    if (tid < 98) {
        int td = tid / 49, rem = tid - td * 49, th = rem / 7, tw = rem - th * 7;
        int d = wd * 2 + td, h = wh * 7 + th, w = ww * 7 + tw;
        int dr = d < 2 ? 0 : (d < 3 ? 1 : 2);
        int hr = h < 49 ? 0 : (h < 53 ? 1 : 2);
        int wr = w < 49 ? 0 : (w < 53 ? 1 : 2);
        lab[tid] = dr * 9 + hr * 3 + wr;
    }

    // load q,k,v tiles vectorized (784 float4 each)
    const float4* base4 = (const float4*)(qkv + (long long)win * 98 * 384 + head * 32);
    float4* qs4 = (float4*)qs;
    float4* ks4 = (float4*)ks;
    float4* vs4 = (float4*)vs;
    for (int idx = tid; idx < 784; idx += 256) {
        int i = idx >> 3, c4 = idx & 7;
        const float4* r = base4 + i * 96 + c4;   // 384 floats = 96 float4
        float4 qv = r[0];
        qv.x *= SCALE_Q; qv.y *= SCALE_Q; qv.z *= SCALE_Q; qv.w *= SCALE_Q;
        qs4[idx] = qv;
        ks4[idx] = r[32];
        vs4[idx] = r[64];
    }
    __syncthreads();

    // S = qk^T + bias + mask; thread computes (i, j0..j0+3)
    for (int t = tid; t < 98 * 25; t += 256) {
        int i = t / 25, j0 = (t - i * 25) * 4;
        float acc0 = 0.f, acc1 = 0.f, acc2 = 0.f, acc3 = 0.f;
        const float4* q4 = qs4 + i * 8;
        const float4* k0 = ks4 + j0 * 8;
        #pragma unroll
        for (int c = 0; c < 8; c++) {
            float4 qv = q4[c];
            float4 k_0 = k0[c], k_1 = k0[8 + c], k_2 = k0[16 + c], k_3 = k0[24 + c];
            acc0 += qv.x * k_0.x + qv.y * k_0.y + qv.z * k_0.z + qv.w * k_0.w;
            acc1 += qv.x * k_1.x + qv.y * k_1.y + qv.z * k_1.z + qv.w * k_1.w;
            acc2 += qv.x * k_2.x + qv.y * k_2.y + qv.z * k_2.z + qv.w * k_2.w;
            acc3 += qv.x * k_3.x + qv.y * k_3.y + qv.z * k_3.z + qv.w * k_3.w;
        }
        int di = i / 49, ri = i - di * 49, hi = ri / 7, wi = ri - hi * 7;
        int li = lab[i];
        float accs[4] = {acc0, acc1, acc2, acc3};
        #pragma unroll
        for (int jj = 0; jj < 4; jj++) {
            int j = j0 + jj;
            if (j < 98) {
                int dj = j / 49, rj = j - dj * 49, hj = rj / 7, wj = rj - hj * 7;
                int rel = (di - dj + 1) * 169 + (hi - hj + 6) * 13 + (wi - wj + 6);
                float bias = rpb[rel * 4 + head];
                float msk  = (li == lab[j]) ? 0.f : -100.f;
                ss[i * 100 + j] = accs[jj] + bias + msk;
            }
        }
    }
    __syncthreads();

    // warp-per-row softmax
    {
        int wid = tid >> 5, lane = tid & 31;
        for (int row = wid; row < 98; row += 8) {
            float* r = ss + row * 100;
            float mx = -1e30f;
            for (int j = lane; j < 98; j += 32) mx = fmaxf(mx, r[j]);
            #pragma unroll
            for (int o = 16; o; o >>= 1) mx = fmaxf(mx, __shfl_xor_sync(0xffffffffu, mx, o));
            float sum = 0.f;
            for (int j = lane; j < 98; j += 32) { float e = __expf(r[j] - mx); r[j] = e; sum += e; }
            #pragma unroll
            for (int o = 16; o; o >>= 1) sum += __shfl_xor_sync(0xffffffffu, sum, o);
            float inv = 1.f / sum;
            for (int j = lane; j < 98; j += 32) r[j] *= inv;
        }
    }
    __syncthreads();

    // out = P @ V; thread computes float4 (i, 4c)
    float* obase = out + (long long)win * 98 * 128 + head * 32;
    for (int t = tid; t < 98 * 8; t += 256) {
        int i = t >> 3, cc = t & 7;
        float4 acc = make_float4(0.f, 0.f, 0.f, 0.f);
        const float* pr = ss + i * 100;
        const float4* v4 = vs4 + cc;
        #pragma unroll 14
        for (int j = 0; j < 98; j++) {
            float p = pr[j];
            float4 vv = v4[j * 8];
            acc.x += p * vv.x; acc.y += p * vv.y; acc.z += p * vv.z; acc.w += p * vv.w;
        }
        *(float4*)(obase + (long long)i * 128 + cc * 4) = acc;
    }
}

// ---------------------------------------------------------------------------
// TF32 tensor-core GEMM: C = act(A[M,K] @ B[K,N] + bias) (+ epilogue)
// BM=BN=128, BK=32, 256 threads, 8 warps of 64x32, mma.m16n8k8.
// cp.async 2-stage pipeline.  M%128==0, N%128==0, K%32==0.
// ---------------------------------------------------------------------------
#define AS_STRIDE 36
#define BS_STRIDE 136
#define STAGE_FLOATS (128 * AS_STRIDE + 32 * BS_STRIDE)   // 8960
#define GEMM_SMEM (2 * STAGE_FLOATS * 4)                  // 71680 B

__device__ __forceinline__ void cp16(float* dst, const float* src)
{
    uint32_t d = (uint32_t)__cvta_generic_to_shared(dst);
    asm volatile("cp.async.ca.shared.global [%0], [%1], 16;\n" :: "r"(d), "l"(src));
}
__device__ __forceinline__ uint32_t f2tf32(float f)
{
    uint32_t u;
    asm("cvt.rna.tf32.f32 %0, %1;\n" : "=r"(u) : "f"(f));
    return u;
}
__device__ __forceinline__ void mma_tf32(float c[4], const uint32_t a[4], const uint32_t b[2])
{
    asm volatile(
        "mma.sync.aligned.m16n8k8.row.col.f32.tf32.tf32.f32 "
        "{%0,%1,%2,%3}, {%4,%5,%6,%7}, {%8,%9}, {%0,%1,%2,%3};\n"
        : "+f"(c[0]), "+f"(c[1]), "+f"(c[2]), "+f"(c[3])
        : "r"(a[0]), "r"(a[1]), "r"(a[2]), "r"(a[3]), "r"(b[0]), "r"(b[1]));
}

template<int ACT, int EPI>
__global__ void __launch_bounds__(256, 2)
gemm_kernel(const float* __restrict__ A, const float* __restrict__ B,
            const float* __restrict__ bias, float* __restrict__ C,
            const float* __restrict__ res, int M, int N, int K)
{
    extern __shared__ float gsm[];
    int tid = threadIdx.x;
    int m0 = blockIdx.y * 128;
    int n0 = blockIdx.x * 128;

    int w    = tid >> 5, lane = tid & 31;
    int g    = lane >> 2, tg = lane & 3;
    int wm   = (w & 1) * 64;
    int wn   = (w >> 1) * 32;

    float c[4][4][4];
    #pragma unroll
    for (int mf = 0; mf < 4; mf++)
        #pragma unroll
        for (int nf = 0; nf < 4; nf++)
            #pragma unroll
            for (int r = 0; r < 4; r++) c[mf][nf][r] = 0.f;

    const int KT = K >> 5;

    auto load_stage = [&](int stage, int k0) {
        float* As = gsm + stage * STAGE_FLOATS;
        float* Bs = As + 128 * AS_STRIDE;
        #pragma unroll
        for (int r = 0; r < 4; r++) {
            int q = tid + r * 256;
            int arow = q >> 3, acw = q & 7;
            cp16(As + arow * AS_STRIDE + acw * 4,
                 A + (long long)(m0 + arow) * K + k0 + acw * 4);
            int brow = q >> 5, bcw = q & 31;
            cp16(Bs + brow * BS_STRIDE + bcw * 4,
                 B + (long long)(k0 + brow) * N + n0 + bcw * 4);
        }
    };

    load_stage(0, 0);
    asm volatile("cp.async.commit_group;\n");

    for (int kt = 0; kt < KT; kt++) {
        if (kt + 1 < KT) load_stage((kt + 1) & 1, (kt + 1) << 5);
        asm volatile("cp.async.commit_group;\n");
        asm volatile("cp.async.wait_group 1;\n");
        __syncthreads();

        const float* As = gsm + (kt & 1) * STAGE_FLOATS;
        const float* Bs = As + 128 * AS_STRIDE;

        #pragma unroll
        for (int ks = 0; ks < 4; ks++) {
            int kb = ks * 8;
            uint32_t a[4][4], b[4][2];
            #pragma unroll
            for (int mf = 0; mf < 4; mf++) {
                int row = wm + mf * 16 + g;
                // m16n8k8 tf32 A fragment order:
                // a0=(g,tg) a1=(g+8,tg) a2=(g,tg+4) a3=(g+8,tg+4)
                a[mf][0] = f2tf32(As[row * AS_STRIDE + kb + tg]);
                a[mf][1] = f2tf32(As[(row + 8) * AS_STRIDE + kb + tg]);
                a[mf][2] = f2tf32(As[row * AS_STRIDE + kb + tg + 4]);
                a[mf][3] = f2tf32(As[(row + 8) * AS_STRIDE + kb + tg + 4]);
            }
            #pragma unroll
            for (int nf = 0; nf < 4; nf++) {
                int col = wn + nf * 8 + g;
                // B fragment: b0=(tg,col) b1=(tg+4,col)
                b[nf][0] = f2tf32(Bs[(kb + tg) * BS_STRIDE + col]);
                b[nf][1] = f2tf32(Bs[(kb + tg + 4) * BS_STRIDE + col]);
            }
            #pragma unroll
            for (int mf = 0; mf < 4; mf++)
                #pragma unroll
                for (int nf = 0; nf < 4; nf++)
                    mma_tf32(c[mf][nf], a[mf], b[nf]);
        }
        __syncthreads();
    }

    // epilogue: c0,c1 -> (row g, cols 2tg,2tg+1); c2,c3 -> (row g+8, ...)
    #pragma unroll
    for (int mf = 0; mf < 4; mf++) {
        int r0 = m0 + wm + mf * 16 + g;
        int r1 = r0 + 8;
        long long d0 = r0, d1 = r1;
        if (EPI == 1) { d0 = map_winrow_to_token(r0); d1 = map_winrow_to_token(r1); }
        #pragma unroll
        for (int nf = 0; nf < 4; nf++) {
            int col = n0 + wn + nf * 8 + tg * 2;
            float b0 = bias[col], b1 = bias[col + 1];
            #pragma unroll
            for (int half = 0; half < 2; half++) {
                long long row = half ? r1 : r0;
                long long dst = half ? d1 : d0;
                float v0 = c[mf][nf][half * 2 + 0] + b0;
                float v1 = c[mf][nf][half * 2 + 1] + b1;
                if (ACT == 1) {
                    v0 = 0.5f * v0 * (1.f + erff(v0 * 0.70710678118654752f));
                    v1 = 0.5f * v1 * (1.f + erff(v1 * 0.70710678118654752f));
                }
                if (EPI == 0) {
                    C[row * N + col]     = v0;
                    C[row * N + col + 1] = v1;
                } else if (EPI == 1) {
                    C[dst * 128 + col]     = res[dst * 128 + col] + v0;
                    C[dst * 128 + col + 1] = res[dst * 128 + col + 1] + v1;
                } else {
                    C[row * N + col]     = res[row * N + col] + v0;
                    C[row * N + col + 1] = res[row * N + col + 1] + v1;
                }
            }
        }
    }
}

// ---------------------------------------------------------------------------
// launch
// ---------------------------------------------------------------------------
extern "C" void kernel_launch(void* const* d_in, const int* in_sizes, int n_in,
                              void* d_out, int out_size)
{
    const float* x       = (const float*)d_in[0];
    const float* norm1_g = (const float*)d_in[1];
    const float* norm1_b = (const float*)d_in[2];
    const float* qkv_w   = (const float*)d_in[3];
    const float* qkv_b   = (const float*)d_in[4];
    const float* rpb     = (const float*)d_in[5];
    const float* proj_w  = (const float*)d_in[6];
    const float* proj_b  = (const float*)d_in[7];
    const float* norm2_g = (const float*)d_in[8];
    const float* norm2_b = (const float*)d_in[9];
    const float* fc1_w   = (const float*)d_in[10];
    const float* fc1_b   = (const float*)d_in[11];
    const float* fc2_w   = (const float*)d_in[12];
    const float* fc2_b   = (const float*)d_in[13];
    float* out = (float*)d_out;

    float *xw, *qkv, *att, *x1, *h2, *hid;
    cudaGetSymbolAddress((void**)&xw,  g_xw);
    cudaGetSymbolAddress((void**)&qkv, g_qkv);
    cudaGetSymbolAddress((void**)&att, g_att);
    cudaGetSymbolAddress((void**)&x1,  g_x1);
    cudaGetSymbolAddress((void**)&h2,  g_h2);
    cudaGetSymbolAddress((void**)&hid, g_hid);

    cudaFuncSetAttribute(attn_kernel, cudaFuncAttributeMaxDynamicSharedMemorySize, ATTN_SMEM);
    cudaFuncSetAttribute(gemm_kernel<0,0>, cudaFuncAttributeMaxDynamicSharedMemorySize, GEMM_SMEM);
    cudaFuncSetAttribute(gemm_kernel<0,1>, cudaFuncAttributeMaxDynamicSharedMemorySize, GEMM_SMEM);
    cudaFuncSetAttribute(gemm_kernel<1,0>, cudaFuncAttributeMaxDynamicSharedMemorySize, GEMM_SMEM);
    cudaFuncSetAttribute(gemm_kernel<0,2>, cudaFuncAttributeMaxDynamicSharedMemorySize, GEMM_SMEM);

    // 1) LN1 + shift + window partition
    ln_kernel<<<Bn_TOK, 128>>>(x, norm1_g, norm1_b, xw, 1);

    // 2) QKV projection
    gemm_kernel<0, 0><<<dim3(3, Bn_TOK / 128), 256, GEMM_SMEM>>>(
        xw, qkv_w, qkv_b, qkv, nullptr, Bn_TOK, 384, 128);

    // 3) windowed attention
    attn_kernel<<<NWIN * 4, 256, ATTN_SMEM>>>(qkv, rpb, att);

    // 4) proj + window reverse + unshift + residual
    gemm_kernel<0, 1><<<dim3(1, Bn_TOK / 128), 256, GEMM_SMEM>>>(
        att, proj_w, proj_b, x1, x, Bn_TOK, 128, 128);

    // 5) LN2
    ln_kernel<<<Bn_TOK, 128>>>(x1, norm2_g, norm2_b, h2, 0);

    // 6) fc1 + GELU
    gemm_kernel<1, 0><<<dim3(4, Bn_TOK / 128), 256, GEMM_SMEM>>>(
        h2, fc1_w, fc1_b, hid, nullptr, Bn_TOK, 512, 128);

    // 7) fc2 + residual -> out
    gemm_kernel<0, 2><<<dim3(1, Bn_TOK / 128), 256, GEMM_SMEM>>>(
        hid, fc2_w, fc2_b, out, x1, Bn_TOK, 128, 512);
}

// round 8
// speedup vs baseline: 1.6199x; 1.1213x over previous
#include <cuda_runtime.h>
#include <cuda_bf16.h>
#include <math.h>
#include <stdint.h>

typedef __nv_bfloat16  bf16;
typedef __nv_bfloat162 bf162;

// ---------------------------------------------------------------------------
// Problem constants
// ---------------------------------------------------------------------------
#define Bn_TOK   100352      // 8*4*56*56 = 1024 windows * 98
#define NWIN     1024
#define SCALE_Q  0.17677669529663687f   // 32^-0.5
#define LN_EPS   1e-5f

// ---------------------------------------------------------------------------
// Scratch: bf16 activations, fp32 residual spine, bf16 weight copies
// ---------------------------------------------------------------------------
__device__ bf16  g_xw  [(long long)Bn_TOK * 128];
__device__ bf16  g_qkv [(long long)Bn_TOK * 384];
__device__ bf16  g_att [(long long)Bn_TOK * 128];
__device__ float g_x1  [(long long)Bn_TOK * 128];
__device__ bf16  g_h2  [(long long)Bn_TOK * 128];
__device__ bf16  g_hid [(long long)Bn_TOK * 512];
__device__ bf16  g_wqkv[128 * 384];
__device__ bf16  g_wproj[128 * 128];
__device__ bf16  g_wfc1[128 * 512];
__device__ bf16  g_wfc2[512 * 128];

// ---------------------------------------------------------------------------
// fp32 -> bf16 conversion
// ---------------------------------------------------------------------------
__global__ void f2bf_kernel(const float* __restrict__ s, bf16* __restrict__ d, int n)
{
    int i = blockIdx.x * 256 + threadIdx.x;
    if (i < n) d[i] = __float2bfloat16(s[i]);
}

// ---------------------------------------------------------------------------
// window-row -> original token index (shift (1,3,3), window (2,7,7))
// ---------------------------------------------------------------------------
__device__ __forceinline__ int map_winrow_to_token(int row)
{
    int win = row / 98, n = row - win * 98;
    int b    = win >> 7;
    int winS = win & 127;
    int wd = winS >> 6, wh = (winS >> 3) & 7, ww = winS & 7;
    int td = n / 49, rem = n - td * 49, th = rem / 7, tw = rem - th * 7;
    int d = wd * 2 + td;
    int h = wh * 7 + th;
    int w = ww * 7 + tw;
    int ds = (d + 1) & 3;
    int hs = h + 3; if (hs >= 56) hs -= 56;
    int ws = w + 3; if (ws >= 56) ws -= 56;
    return ((b * 4 + ds) * 56 + hs) * 56 + ws;
}

// ---------------------------------------------------------------------------
// LayerNorm -> bf16 output. One block per token, 128 threads.
// ---------------------------------------------------------------------------
__global__ void ln_kernel(const float* __restrict__ in,
                          const float* __restrict__ gam,
                          const float* __restrict__ bet,
                          bf16* __restrict__ out, int gather)
{
    int row = blockIdx.x;
    int tid = threadIdx.x;
    int src = gather ? map_winrow_to_token(row) : row;
    float v = in[(long long)src * 128 + tid];

    float s = v, s2 = v * v;
    #pragma unroll
    for (int o = 16; o; o >>= 1) {
        s  += __shfl_down_sync(0xffffffffu, s,  o);
        s2 += __shfl_down_sync(0xffffffffu, s2, o);
    }
    __shared__ float red[8];
    __shared__ float s_mu, s_rs;
    int wid = tid >> 5;
    if ((tid & 31) == 0) { red[wid] = s; red[4 + wid] = s2; }
    __syncthreads();
    if (tid == 0) {
        float su = red[0] + red[1] + red[2] + red[3];
        float sq = red[4] + red[5] + red[6] + red[7];
        float mu  = su * (1.f / 128.f);
        float var = sq * (1.f / 128.f) - mu * mu;
        s_mu = mu;
        s_rs = rsqrtf(var + LN_EPS);
    }
    __syncthreads();
    out[(long long)row * 128 + tid] =
        __float2bfloat16((v - s_mu) * s_rs * gam[tid] + bet[tid]);
}

// ---------------------------------------------------------------------------
// Fused windowed attention (fp32 compute in smem, bf16 in/out).
// 256 threads per (window, head) block.
// ---------------------------------------------------------------------------
#define ATTN_SMEM ((3 * 3136 + 98 * 100) * 4)   // 76832 B dynamic

__global__ void __launch_bounds__(256)
attn_kernel(const bf16* __restrict__ qkv,
            const float* __restrict__ rpb,
            bf16* __restrict__ out)
{
    int blk  = blockIdx.x;
    int win  = blk >> 2;
    int head = blk & 3;
    int tid  = threadIdx.x;

    extern __shared__ float sm[];
    float* qs = sm;                 // 98*32
    float* ks = sm + 3136;
    float* vs = sm + 6272;
    float* ss = sm + 9408;          // 98 * 100 (padded)
    __shared__ int lab[98];

    int winS = win & 127;
    int wd = winS >> 6, wh = (winS >> 3) & 7, ww = winS & 7;
    if (tid < 98) {
        int td = tid / 49, rem = tid - td * 49, th = rem / 7, tw = rem - th * 7;
        int d = wd * 2 + td, h = wh * 7 + th, w = ww * 7 + tw;
        int dr = d < 2 ? 0 : (d < 3 ? 1 : 2);
        int hr = h < 49 ? 0 : (h < 53 ? 1 : 2);
        int wr = w < 49 ? 0 : (w < 53 ? 1 : 2);
        lab[tid] = dr * 9 + hr * 3 + wr;
    }

    // load q,k,v (bf16 -> fp32 smem); each idx covers 4 elements
    const bf16* base = qkv + (long long)win * 98 * 384 + head * 32;
    float4* qs4 = (float4*)qs;
    float4* ks4 = (float4*)ks;
    float4* vs4 = (float4*)vs;
    for (int idx = tid; idx < 784; idx += 256) {
        int i = idx >> 3, c4 = idx & 7;
        const bf162* p = (const bf162*)(base + i * 384 + c4 * 4);
        float2 q01 = __bfloat1622float2(p[0]);
        float2 q23 = __bfloat1622float2(p[1]);
        float2 k01 = __bfloat1622float2(p[64]);
        float2 k23 = __bfloat1622float2(p[65]);
        float2 v01 = __bfloat1622float2(p[128]);
        float2 v23 = __bfloat1622float2(p[129]);
        qs4[idx] = make_float4(q01.x * SCALE_Q, q01.y * SCALE_Q,
                               q23.x * SCALE_Q, q23.y * SCALE_Q);
        ks4[idx] = make_float4(k01.x, k01.y, k23.x, k23.y);
        vs4[idx] = make_float4(v01.x, v01.y, v23.x, v23.y);
    }
    __syncthreads();

    // S = qk^T + bias + mask; thread computes (i, j0..j0+3)
    for (int t = tid; t < 98 * 25; t += 256) {
        int i = t / 25, j0 = (t - i * 25) * 4;
        float acc0 = 0.f, acc1 = 0.f, acc2 = 0.f, acc3 = 0.f;
        const float4* q4 = qs4 + i * 8;
        const float4* k0 = ks4 + j0 * 8;
        #pragma unroll
        for (int c = 0; c < 8; c++) {
            float4 qv = q4[c];
            float4 k_0 = k0[c], k_1 = k0[8 + c], k_2 = k0[16 + c], k_3 = k0[24 + c];
            acc0 += qv.x * k_0.x + qv.y * k_0.y + qv.z * k_0.z + qv.w * k_0.w;
            acc1 += qv.x * k_1.x + qv.y * k_1.y + qv.z * k_1.z + qv.w * k_1.w;
            acc2 += qv.x * k_2.x + qv.y * k_2.y + qv.z * k_2.z + qv.w * k_2.w;
            acc3 += qv.x * k_3.x + qv.y * k_3.y + qv.z * k_3.z + qv.w * k_3.w;
        }
        int di = i / 49, ri = i - di * 49, hi = ri / 7, wi = ri - hi * 7;
        int li = lab[i];
        float accs[4] = {acc0, acc1, acc2, acc3};
        #pragma unroll
        for (int jj = 0; jj < 4; jj++) {
            int j = j0 + jj;
            if (j < 98) {
                int dj = j / 49, rj = j - dj * 49, hj = rj / 7, wj = rj - hj * 7;
                int rel = (di - dj + 1) * 169 + (hi - hj + 6) * 13 + (wi - wj + 6);
                float bias = rpb[rel * 4 + head];
                float msk  = (li == lab[j]) ? 0.f : -100.f;
                ss[i * 100 + j] = accs[jj] + bias + msk;
            }
        }
    }
    __syncthreads();

    // warp-per-row softmax
    {
        int wid = tid >> 5, lane = tid & 31;
        for (int row = wid; row < 98; row += 8) {
            float* r = ss + row * 100;
            float mx = -1e30f;
            for (int j = lane; j < 98; j += 32) mx = fmaxf(mx, r[j]);
            #pragma unroll
            for (int o = 16; o; o >>= 1) mx = fmaxf(mx, __shfl_xor_sync(0xffffffffu, mx, o));
            float sum = 0.f;
            for (int j = lane; j < 98; j += 32) { float e = __expf(r[j] - mx); r[j] = e; sum += e; }
            #pragma unroll
            for (int o = 16; o; o >>= 1) sum += __shfl_xor_sync(0xffffffffu, sum, o);
            float inv = 1.f / sum;
            for (int j = lane; j < 98; j += 32) r[j] *= inv;
        }
    }
    __syncthreads();

    // out = P @ V -> bf16
    bf16* obase = out + (long long)win * 98 * 128 + head * 32;
    for (int t = tid; t < 98 * 8; t += 256) {
        int i = t >> 3, cc = t & 7;
        float4 acc = make_float4(0.f, 0.f, 0.f, 0.f);
        const float* pr = ss + i * 100;
        const float4* v4 = vs4 + cc;
        #pragma unroll 14
        for (int j = 0; j < 98; j++) {
            float p = pr[j];
            float4 vv = v4[j * 8];
            acc.x += p * vv.x; acc.y += p * vv.y; acc.z += p * vv.z; acc.w += p * vv.w;
        }
        bf162* po = (bf162*)(obase + (long long)i * 128 + cc * 4);
        po[0] = __floats2bfloat162_rn(acc.x, acc.y);
        po[1] = __floats2bfloat162_rn(acc.z, acc.w);
    }
}

// ---------------------------------------------------------------------------
// bf16 tensor-core GEMM: C = act(A[M,K] @ B[K,N] + bias) (+ epilogue)
// BM=BN=128, BK=32, 256 threads (8 warps of 64x32), mma.m16n8k16,
// ldmatrix operand loads, 3-stage cp.async pipeline.
// EPI 0: store          EPI 1: scatter + residual   EPI 2: add residual
// OUTBF 1: bf16 output, else fp32
// ---------------------------------------------------------------------------
#define AS_STR 40     // bf16 elems per A smem row (32 + 8 pad)
#define BS_STR 136    // bf16 elems per B smem row (128 + 8 pad)
#define STAGE_ELEMS (128 * AS_STR + 32 * BS_STR)   // 9472 bf16
#define NSTAGE 3
#define GEMM_SMEM (NSTAGE * STAGE_ELEMS * 2)       // 56832 B

__device__ __forceinline__ void cp16(void* dst, const void* src)
{
    uint32_t d = (uint32_t)__cvta_generic_to_shared(dst);
    asm volatile("cp.async.ca.shared.global [%0], [%1], 16;\n" :: "r"(d), "l"(src));
}
__device__ __forceinline__ void ldm_x4(uint32_t& r0, uint32_t& r1, uint32_t& r2,
                                       uint32_t& r3, const bf16* p)
{
    uint32_t a = (uint32_t)__cvta_generic_to_shared(p);
    asm volatile("ldmatrix.sync.aligned.m8n8.x4.shared.b16 {%0,%1,%2,%3}, [%4];\n"
                 : "=r"(r0), "=r"(r1), "=r"(r2), "=r"(r3) : "r"(a));
}
__device__ __forceinline__ void ldm_x4_t(uint32_t& r0, uint32_t& r1, uint32_t& r2,
                                         uint32_t& r3, const bf16* p)
{
    uint32_t a = (uint32_t)__cvta_generic_to_shared(p);
    asm volatile("ldmatrix.sync.aligned.m8n8.x4.trans.shared.b16 {%0,%1,%2,%3}, [%4];\n"
                 : "=r"(r0), "=r"(r1), "=r"(r2), "=r"(r3) : "r"(a));
}
__device__ __forceinline__ void mma_bf16(float c[4], const uint32_t a[4], const uint32_t b[2])
{
    asm volatile(
        "mma.sync.aligned.m16n8k16.row.col.f32.bf16.bf16.f32 "
        "{%0,%1,%2,%3}, {%4,%5,%6,%7}, {%8,%9}, {%0,%1,%2,%3};\n"
        : "+f"(c[0]), "+f"(c[1]), "+f"(c[2]), "+f"(c[3])
        : "r"(a[0]), "r"(a[1]), "r"(a[2]), "r"(a[3]), "r"(b[0]), "r"(b[1]));
}

template<int ACT, int EPI, int OUTBF>
__global__ void __launch_bounds__(256, 2)
gemm_bf(const bf16* __restrict__ A, const bf16* __restrict__ B,
        const float* __restrict__ bias, void* __restrict__ Cv,
        const float* __restrict__ res, int M, int N, int K)
{
    extern __shared__ bf16 gsm[];
    int tid = threadIdx.x;
    int m0 = blockIdx.y * 128;
    int n0 = blockIdx.x * 128;

    int w    = tid >> 5, lane = tid & 31;
    int g    = lane >> 2, tg = lane & 3;
    int wm   = (w & 1) * 64;
    int wn   = (w >> 1) * 32;
    int t1   = (lane >> 3) & 1;       // ldmatrix tile row-half
    int t2   = (lane >> 4);           // ldmatrix tile col-half
    int rr   = lane & 7;              // ldmatrix row within 8x8

    float c[4][4][4];
    #pragma unroll
    for (int mf = 0; mf < 4; mf++)
        #pragma unroll
        for (int nf = 0; nf < 4; nf++)
            #pragma unroll
            for (int r = 0; r < 4; r++) c[mf][nf][r] = 0.f;

    const int KT = K >> 5;

    auto load_stage = [&](int stage, int kt) {
        bf16* As = gsm + stage * STAGE_ELEMS;
        bf16* Bs = As + 128 * AS_STR;
        int k0 = kt << 5;
        #pragma unroll
        for (int r = 0; r < 2; r++) {
            int q = tid + r * 256;
            int arow = q >> 2, ac = q & 3;             // 128 rows x 4 chunks of 8
            cp16(As + arow * AS_STR + ac * 8,
                 A + (long long)(m0 + arow) * K + k0 + ac * 8);
            int brow = q >> 4, bc = q & 15;            // 32 rows x 16 chunks of 8
            cp16(Bs + brow * BS_STR + bc * 8,
                 B + (long long)(k0 + brow) * N + n0 + bc * 8);
        }
    };

    load_stage(0, 0);
    asm volatile("cp.async.commit_group;\n");
    load_stage(1, 1);
    asm volatile("cp.async.commit_group;\n");

    for (int kt = 0; kt < KT; kt++) {
        asm volatile("cp.async.wait_group 1;\n");
        __syncthreads();

        if (kt + 2 < KT) load_stage((kt + 2) % NSTAGE, kt + 2);
        asm volatile("cp.async.commit_group;\n");

        const bf16* As = gsm + (kt % NSTAGE) * STAGE_ELEMS;
        const bf16* Bs = As + 128 * AS_STR;

        #pragma unroll
        for (int ks = 0; ks < 2; ks++) {
            int kb = ks * 16;
            uint32_t a[4][4], b[4][2];
            #pragma unroll
            for (int mf = 0; mf < 4; mf++)
                ldm_x4(a[mf][0], a[mf][1], a[mf][2], a[mf][3],
                       As + (wm + mf * 16 + t1 * 8 + rr) * AS_STR + kb + t2 * 8);
            #pragma unroll
            for (int nh = 0; nh < 2; nh++) {
                uint32_t r0, r1, r2, r3;
                ldm_x4_t(r0, r1, r2, r3,
                         Bs + (kb + t1 * 8 + rr) * BS_STR + wn + nh * 16 + t2 * 8);
                b[nh * 2][0] = r0; b[nh * 2][1] = r1;
                b[nh * 2 + 1][0] = r2; b[nh * 2 + 1][1] = r3;
            }
            #pragma unroll
            for (int mf = 0; mf < 4; mf++)
                #pragma unroll
                for (int nf = 0; nf < 4; nf++)
                    mma_bf16(c[mf][nf], a[mf], b[nf]);
        }
    }

    // epilogue: c0,c1 -> (row g, cols 2tg,2tg+1); c2,c3 -> (row g+8, ...)
    float* Cf = (float*)Cv;
    bf16*  Cb = (bf16*)Cv;
    #pragma unroll
    for (int mf = 0; mf < 4; mf++) {
        int r0 = m0 + wm + mf * 16 + g;
        int r1 = r0 + 8;
        long long d0 = r0, d1 = r1;
        if (EPI == 1) { d0 = map_winrow_to_token(r0); d1 = map_winrow_to_token(r1); }
        #pragma unroll
        for (int nf = 0; nf < 4; nf++) {
            int col = n0 + wn + nf * 8 + tg * 2;
            float b0 = bias[col], b1 = bias[col + 1];
            #pragma unroll
            for (int half = 0; half < 2; half++) {
                long long row = half ? r1 : r0;
                long long dst = half ? d1 : d0;
                float v0 = c[mf][nf][half * 2 + 0] + b0;
                float v1 = c[mf][nf][half * 2 + 1] + b1;
                if (ACT == 1) {
                    v0 = 0.5f * v0 * (1.f + erff(v0 * 0.70710678118654752f));
                    v1 = 0.5f * v1 * (1.f + erff(v1 * 0.70710678118654752f));
                }
                if (EPI == 1) {
                    float2 rv = *(const float2*)(res + dst * 128 + col);
                    *(float2*)(Cf + dst * 128 + col) = make_float2(rv.x + v0, rv.y + v1);
                } else if (EPI == 2) {
                    float2 rv = *(const float2*)(res + row * N + col);
                    *(float2*)(Cf + row * N + col) = make_float2(rv.x + v0, rv.y + v1);
                } else if (OUTBF) {
                    *(bf162*)(Cb + row * N + col) = __floats2bfloat162_rn(v0, v1);
                } else {
                    *(float2*)(Cf + row * N + col) = make_float2(v0, v1);
                }
            }
        }
    }
}

// ---------------------------------------------------------------------------
// launch
// ---------------------------------------------------------------------------
extern "C" void kernel_launch(void* const* d_in, const int* in_sizes, int n_in,
                              void* d_out, int out_size)
{
    const float* x       = (const float*)d_in[0];
    const float* norm1_g = (const float*)d_in[1];
    const float* norm1_b = (const float*)d_in[2];
    const float* qkv_w   = (const float*)d_in[3];
    const float* qkv_b   = (const float*)d_in[4];
    const float* rpb     = (const float*)d_in[5];
    const float* proj_w  = (const float*)d_in[6];
    const float* proj_b  = (const float*)d_in[7];
    const float* norm2_g = (const float*)d_in[8];
    const float* norm2_b = (const float*)d_in[9];
    const float* fc1_w   = (const float*)d_in[10];
    const float* fc1_b   = (const float*)d_in[11];
    const float* fc2_w   = (const float*)d_in[12];
    const float* fc2_b   = (const float*)d_in[13];
    float* out = (float*)d_out;

    bf16 *xw, *qkv, *att, *h2, *hid, *wqkv, *wproj, *wfc1, *wfc2;
    float *x1;
    cudaGetSymbolAddress((void**)&xw,   g_xw);
    cudaGetSymbolAddress((void**)&qkv,  g_qkv);
    cudaGetSymbolAddress((void**)&att,  g_att);
    cudaGetSymbolAddress((void**)&x1,   g_x1);
    cudaGetSymbolAddress((void**)&h2,   g_h2);
    cudaGetSymbolAddress((void**)&hid,  g_hid);
    cudaGetSymbolAddress((void**)&wqkv, g_wqkv);
    cudaGetSymbolAddress((void**)&wproj,g_wproj);
    cudaGetSymbolAddress((void**)&wfc1, g_wfc1);
    cudaGetSymbolAddress((void**)&wfc2, g_wfc2);

    cudaFuncSetAttribute(attn_kernel, cudaFuncAttributeMaxDynamicSharedMemorySize, ATTN_SMEM);
    // every instantiation that gets LAUNCHED must have its dyn-smem cap raised
    cudaFuncSetAttribute(gemm_bf<0,0,1>, cudaFuncAttributeMaxDynamicSharedMemorySize, GEMM_SMEM);
    cudaFuncSetAttribute(gemm_bf<0,1,0>, cudaFuncAttributeMaxDynamicSharedMemorySize, GEMM_SMEM);
    cudaFuncSetAttribute(gemm_bf<1,0,1>, cudaFuncAttributeMaxDynamicSharedMemorySize, GEMM_SMEM);
    cudaFuncSetAttribute(gemm_bf<0,2,0>, cudaFuncAttributeMaxDynamicSharedMemorySize, GEMM_SMEM);

    // 0) weight conversion (independent of activations)
    f2bf_kernel<<<(128 * 384 + 255) / 256, 256>>>(qkv_w,  wqkv,  128 * 384);
    f2bf_kernel<<<(128 * 128 + 255) / 256, 256>>>(proj_w, wproj, 128 * 128);
    f2bf_kernel<<<(128 * 512 + 255) / 256, 256>>>(fc1_w,  wfc1,  128 * 512);
    f2bf_kernel<<<(512 * 128 + 255) / 256, 256>>>(fc2_w,  wfc2,  512 * 128);

    // 1) LN1 + shift + window partition -> bf16
    ln_kernel<<<Bn_TOK, 128>>>(x, norm1_g, norm1_b, xw, 1);

    // 2) QKV projection -> bf16
    gemm_bf<0, 0, 1><<<dim3(3, Bn_TOK / 128), 256, GEMM_SMEM>>>(
        xw, wqkv, qkv_b, qkv, nullptr, Bn_TOK, 384, 128);

    // 3) windowed attention -> bf16
    attn_kernel<<<NWIN * 4, 256, ATTN_SMEM>>>(qkv, rpb, att);

    // 4) proj + window reverse + unshift + residual -> fp32 x1
    gemm_bf<0, 1, 0><<<dim3(1, Bn_TOK / 128), 256, GEMM_SMEM>>>(
        att, wproj, proj_b, x1, x, Bn_TOK, 128, 128);

    // 5) LN2 -> bf16
    ln_kernel<<<Bn_TOK, 128>>>(x1, norm2_g, norm2_b, h2, 0);

    // 6) fc1 + GELU -> bf16
    gemm_bf<1, 0, 1><<<dim3(4, Bn_TOK / 128), 256, GEMM_SMEM>>>(
        h2, wfc1, fc1_b, hid, nullptr, Bn_TOK, 512, 128);

    // 7) fc2 + residual -> fp32 out
    gemm_bf<0, 2, 0><<<dim3(1, Bn_TOK / 128), 256, GEMM_SMEM>>>(
        hid, wfc2, fc2_b, out, x1, Bn_TOK, 128, 512);
}

// round 9
// speedup vs baseline: 5.4802x; 3.3831x over previous
#include <cuda_runtime.h>
#include <cuda_bf16.h>
#include <math.h>
#include <stdint.h>

typedef __nv_bfloat16  bf16;
typedef __nv_bfloat162 bf162;

// ---------------------------------------------------------------------------
// Problem constants
// ---------------------------------------------------------------------------
#define Bn_TOK   100352      // 8*4*56*56 = 1024 windows * 98
#define NWIN     1024
#define SCALE_Q  0.17677669529663687f   // 32^-0.5
#define LN_EPS   1e-5f

// ---------------------------------------------------------------------------
// Scratch: bf16 activations, fp32 residual spine, bf16 weight copies
// ---------------------------------------------------------------------------
__device__ bf16  g_xw  [(long long)Bn_TOK * 128];
__device__ bf16  g_qkv [(long long)Bn_TOK * 384];
__device__ bf16  g_att [(long long)Bn_TOK * 128];
__device__ float g_x1  [(long long)Bn_TOK * 128];
__device__ bf16  g_h2  [(long long)Bn_TOK * 128];
__device__ bf16  g_hid [(long long)Bn_TOK * 512];
__device__ bf16  g_wqkv[128 * 384];
__device__ bf16  g_wproj[128 * 128];
__device__ bf16  g_wfc1[128 * 512];
__device__ bf16  g_wfc2[512 * 128];

// ---------------------------------------------------------------------------
// helpers
// ---------------------------------------------------------------------------
__global__ void f2bf_kernel(const float* __restrict__ s, bf16* __restrict__ d, int n)
{
    int i = blockIdx.x * 256 + threadIdx.x;
    if (i < n) d[i] = __float2bfloat16(s[i]);
}

__device__ __forceinline__ int map_winrow_to_token(int row)
{
    int win = row / 98, n = row - win * 98;
    int b    = win >> 7;
    int winS = win & 127;
    int wd = winS >> 6, wh = (winS >> 3) & 7, ww = winS & 7;
    int td = n / 49, rem = n - td * 49, th = rem / 7, tw = rem - th * 7;
    int d = wd * 2 + td;
    int h = wh * 7 + th;
    int w = ww * 7 + tw;
    int ds = (d + 1) & 3;
    int hs = h + 3; if (hs >= 56) hs -= 56;
    int ws = w + 3; if (ws >= 56) ws -= 56;
    return ((b * 4 + ds) * 56 + hs) * 56 + ws;
}

// ---------------------------------------------------------------------------
// LayerNorm -> bf16 output. One block per token, 128 threads.
// ---------------------------------------------------------------------------
__global__ void ln_kernel(const float* __restrict__ in,
                          const float* __restrict__ gam,
                          const float* __restrict__ bet,
                          bf16* __restrict__ out, int gather)
{
    int row = blockIdx.x;
    int tid = threadIdx.x;
    int src = gather ? map_winrow_to_token(row) : row;
    float v = in[(long long)src * 128 + tid];

    float s = v, s2 = v * v;
    #pragma unroll
    for (int o = 16; o; o >>= 1) {
        s  += __shfl_down_sync(0xffffffffu, s,  o);
        s2 += __shfl_down_sync(0xffffffffu, s2, o);
    }
    __shared__ float red[8];
    __shared__ float s_mu, s_rs;
    int wid = tid >> 5;
    if ((tid & 31) == 0) { red[wid] = s; red[4 + wid] = s2; }
    __syncthreads();
    if (tid == 0) {
        float su = red[0] + red[1] + red[2] + red[3];
        float sq = red[4] + red[5] + red[6] + red[7];
        float mu  = su * (1.f / 128.f);
        float var = sq * (1.f / 128.f) - mu * mu;
        s_mu = mu;
        s_rs = rsqrtf(var + LN_EPS);
    }
    __syncthreads();
    out[(long long)row * 128 + tid] =
        __float2bfloat16((v - s_mu) * s_rs * gam[tid] + bet[tid]);
}

// ---------------------------------------------------------------------------
// MMA primitives (shared by GEMM and attention)
// ---------------------------------------------------------------------------
__device__ __forceinline__ void cp16(void* dst, const void* src)
{
    uint32_t d = (uint32_t)__cvta_generic_to_shared(dst);
    asm volatile("cp.async.ca.shared.global [%0], [%1], 16;\n" :: "r"(d), "l"(src));
}
__device__ __forceinline__ void ldm_x4(uint32_t& r0, uint32_t& r1, uint32_t& r2,
                                       uint32_t& r3, const bf16* p)
{
    uint32_t a = (uint32_t)__cvta_generic_to_shared(p);
    asm volatile("ldmatrix.sync.aligned.m8n8.x4.shared.b16 {%0,%1,%2,%3}, [%4];\n"
                 : "=r"(r0), "=r"(r1), "=r"(r2), "=r"(r3) : "r"(a));
}
__device__ __forceinline__ void ldm_x4_t(uint32_t& r0, uint32_t& r1, uint32_t& r2,
                                         uint32_t& r3, const bf16* p)
{
    uint32_t a = (uint32_t)__cvta_generic_to_shared(p);
    asm volatile("ldmatrix.sync.aligned.m8n8.x4.trans.shared.b16 {%0,%1,%2,%3}, [%4];\n"
                 : "=r"(r0), "=r"(r1), "=r"(r2), "=r"(r3) : "r"(a));
}
__device__ __forceinline__ void mma_bf16(float c[4], const uint32_t a[4], const uint32_t b[2])
{
    asm volatile(
        "mma.sync.aligned.m16n8k16.row.col.f32.bf16.bf16.f32 "
        "{%0,%1,%2,%3}, {%4,%5,%6,%7}, {%8,%9}, {%0,%1,%2,%3};\n"
        : "+f"(c[0]), "+f"(c[1]), "+f"(c[2]), "+f"(c[3])
        : "r"(a[0]), "r"(a[1]), "r"(a[2]), "r"(a[3]), "r"(b[0]), "r"(b[1]));
}

// ---------------------------------------------------------------------------
// Tensor-core windowed attention. One block per (window, head), 256 threads.
//   S = q @ k^T (bf16 MMA, fp32 acc)  + scale + bias + mask
//   softmax rows (fp32)  -> P (bf16)
//   out = P @ v (bf16 MMA)
// smem layout (bytes):
//   q_s   [128][40] bf16      0     (10240)
//   k_s   [112][40] bf16  10240     ( 8960)
//   v_s   [112][40] bf16  19200     ( 8960)
//   P     [128][120] bf16 28160     (30720)
//   S     [98][104] f32   58880     (40768)
//   rpb_s [507] f32       99648     ( 2028)
//   jd    [112] int      101676     (  448)
// ---------------------------------------------------------------------------
#define ATT2_SMEM 102128

__global__ void __launch_bounds__(256)
attn2_kernel(const bf16* __restrict__ qkv,
             const float* __restrict__ rpb,
             bf16* __restrict__ out)
{
    extern __shared__ char smc[];
    bf16*  q_s   = (bf16*)(smc);
    bf16*  k_s   = (bf16*)(smc + 10240);
    bf16*  v_s   = (bf16*)(smc + 19200);
    bf16*  P     = (bf16*)(smc + 28160);
    float* S     = (float*)(smc + 58880);
    float* rpb_s = (float*)(smc + 99648);
    int*   jd    = (int*)  (smc + 101676);

    int blk  = blockIdx.x;
    int win  = blk >> 2;
    int head = blk & 3;
    int tid  = threadIdx.x;
    int w    = tid >> 5, lane = tid & 31;
    int g    = lane >> 2, tg = lane & 3;
    int t1   = (lane >> 3) & 1;
    int t2   = lane >> 4;
    int rr   = lane & 7;
    int m0   = w * 16;

    // token coordinate table: jd[j] = dj | hj<<4 | wj<<8 | lab<<12
    int winS = win & 127;
    int wd = winS >> 6, wh = (winS >> 3) & 7, ww = winS & 7;
    if (tid < 112) {
        int v = 0;
        if (tid < 98) {
            int td = tid / 49, rem = tid - td * 49, th = rem / 7, tw = rem - th * 7;
            int d = wd * 2 + td, h = wh * 7 + th, wq = ww * 7 + tw;
            int dr = d < 2 ? 0 : (d < 3 ? 1 : 2);
            int hr = h < 49 ? 0 : (h < 53 ? 1 : 2);
            int wr = wq < 49 ? 0 : (wq < 53 ? 1 : 2);
            v = td | (th << 4) | (tw << 8) | ((dr * 9 + hr * 3 + wr) << 12);
        }
        jd[tid] = v;
    }
    // rel-pos table slice for this head (507 entries)
    for (int i = tid; i < 507; i += 256) rpb_s[i] = rpb[i * 4 + head];

    // load q,k,v tiles (16B chunks); zero pad rows of k,v
    const bf16* base = qkv + (long long)win * 98 * 384 + head * 32;
    for (int idx = tid; idx < 98 * 4; idx += 256) {
        int row = idx >> 2, ch = idx & 3;
        const int4* src = (const int4*)(base + row * 384 + ch * 8);
        *(int4*)(q_s + row * 40 + ch * 8) = src[0];
        *(int4*)(k_s + row * 40 + ch * 8) = src[16];   // +128 bf16
        *(int4*)(v_s + row * 40 + ch * 8) = src[32];   // +256 bf16
    }
    int4 zz = make_int4(0, 0, 0, 0);
    for (int idx = tid; idx < 14 * 5; idx += 256) {
        int row = 98 + idx / 5, ch = idx % 5;
        *(int4*)(k_s + row * 40 + ch * 8) = zz;
        *(int4*)(v_s + row * 40 + ch * 8) = zz;
    }
    __syncthreads();

    // ---- S = q @ k^T : warp owns rows [m0, m0+16), 14 n-tiles, K=32 ----
    float c[14][4];
    #pragma unroll
    for (int nt = 0; nt < 14; nt++)
        #pragma unroll
        for (int e = 0; e < 4; e++) c[nt][e] = 0.f;

    #pragma unroll
    for (int kh = 0; kh < 2; kh++) {
        int kb = kh * 16;
        uint32_t a[4];
        ldm_x4(a[0], a[1], a[2], a[3], q_s + (m0 + t1 * 8 + rr) * 40 + kb + t2 * 8);
        #pragma unroll
        for (int np = 0; np < 7; np++) {
            uint32_t r0, r1, r2, r3;
            ldm_x4(r0, r1, r2, r3, k_s + (np * 16 + t1 * 8 + rr) * 40 + kb + t2 * 8);
            uint32_t b0[2] = {r0, r2};
            uint32_t b1[2] = {r1, r3};
            mma_bf16(c[np * 2],     a, b0);
            mma_bf16(c[np * 2 + 1], a, b1);
        }
    }

    // epilogue: S = acc*scale + bias + mask (guarded to 98x98)
    #pragma unroll
    for (int half = 0; half < 2; half++) {
        int i = m0 + g + half * 8;
        if (i < 98) {
            int pi = jd[i];
            int di = pi & 15, hi = (pi >> 4) & 15, wi = (pi >> 8) & 15, li = pi >> 12;
            #pragma unroll
            for (int nt = 0; nt < 14; nt++) {
                #pragma unroll
                for (int e = 0; e < 2; e++) {
                    int j = nt * 8 + tg * 2 + e;
                    if (j < 98) {
                        int pj = jd[j];
                        int dj = pj & 15, hj = (pj >> 4) & 15, wj = (pj >> 8) & 15;
                        int rel = (di - dj + 1) * 169 + (hi - hj + 6) * 13 + (wi - wj + 6);
                        float bias = rpb_s[rel];
                        float msk  = (li == (pj >> 12)) ? 0.f : -100.f;
                        S[i * 104 + j] = c[nt][half * 2 + e] * SCALE_Q + bias + msk;
                    }
                }
            }
        }
    }
    __syncthreads();

    // ---- softmax rows -> P (bf16), zero pad cols ----
    for (int row = w; row < 98; row += 8) {
        const float* r = S + row * 104;
        bf16* pr = P + row * 120;
        float mx = -1e30f;
        for (int j = lane; j < 98; j += 32) mx = fmaxf(mx, r[j]);
        #pragma unroll
        for (int o = 16; o; o >>= 1) mx = fmaxf(mx, __shfl_xor_sync(0xffffffffu, mx, o));
        float sum = 0.f;
        float ev[4];
        #pragma unroll
        for (int q4 = 0; q4 < 4; q4++) {
            int j = lane + q4 * 32;
            float e = (j < 98) ? __expf(r[j] - mx) : 0.f;
            ev[q4] = e;
            sum += e;
        }
        #pragma unroll
        for (int o = 16; o; o >>= 1) sum += __shfl_xor_sync(0xffffffffu, sum, o);
        float inv = 1.f / sum;
        #pragma unroll
        for (int q4 = 0; q4 < 4; q4++) {
            int j = lane + q4 * 32;
            if (j < 112) pr[j] = __float2bfloat16((j < 98) ? ev[q4] * inv : 0.f);
        }
    }
    __syncthreads();

    // ---- out = P @ v : warp rows [m0, m0+16), 4 n-tiles (32 cols), K=112 ----
    float c2[4][4];
    #pragma unroll
    for (int nt = 0; nt < 4; nt++)
        #pragma unroll
        for (int e = 0; e < 4; e++) c2[nt][e] = 0.f;

    #pragma unroll
    for (int kh = 0; kh < 7; kh++) {
        int kb = kh * 16;
        uint32_t a[4];
        ldm_x4(a[0], a[1], a[2], a[3], P + (m0 + t1 * 8 + rr) * 120 + kb + t2 * 8);
        #pragma unroll
        for (int ch = 0; ch < 2; ch++) {
            uint32_t r0, r1, r2, r3;
            ldm_x4_t(r0, r1, r2, r3, v_s + (kb + t1 * 8 + rr) * 40 + ch * 16 + t2 * 8);
            uint32_t b0[2] = {r0, r1};
            uint32_t b1[2] = {r2, r3};
            mma_bf16(c2[ch * 2],     a, b0);
            mma_bf16(c2[ch * 2 + 1], a, b1);
        }
    }

    bf16* obase = out + (long long)win * 98 * 128 + head * 32;
    #pragma unroll
    for (int half = 0; half < 2; half++) {
        int i = m0 + g + half * 8;
        if (i < 98) {
            #pragma unroll
            for (int nt = 0; nt < 4; nt++) {
                int col = nt * 8 + tg * 2;
                *(bf162*)(obase + (long long)i * 128 + col) =
                    __floats2bfloat162_rn(c2[nt][half * 2], c2[nt][half * 2 + 1]);
            }
        }
    }
}

// ---------------------------------------------------------------------------
// bf16 tensor-core GEMM (unchanged from R8 passing kernel)
// ---------------------------------------------------------------------------
#define AS_STR 40
#define BS_STR 136
#define STAGE_ELEMS (128 * AS_STR + 32 * BS_STR)   // 9472 bf16
#define NSTAGE 3
#define GEMM_SMEM (NSTAGE * STAGE_ELEMS * 2)       // 56832 B

template<int ACT, int EPI, int OUTBF>
__global__ void __launch_bounds__(256, 2)
gemm_bf(const bf16* __restrict__ A, const bf16* __restrict__ B,
        const float* __restrict__ bias, void* __restrict__ Cv,
        const float* __restrict__ res, int M, int N, int K)
{
    extern __shared__ bf16 gsm[];
    int tid = threadIdx.x;
    int m0 = blockIdx.y * 128;
    int n0 = blockIdx.x * 128;

    int w    = tid >> 5, lane = tid & 31;
    int g    = lane >> 2, tg = lane & 3;
    int wm   = (w & 1) * 64;
    int wn   = (w >> 1) * 32;
    int t1   = (lane >> 3) & 1;
    int t2   = (lane >> 4);
    int rr   = lane & 7;

    float c[4][4][4];
    #pragma unroll
    for (int mf = 0; mf < 4; mf++)
        #pragma unroll
        for (int nf = 0; nf < 4; nf++)
            #pragma unroll
            for (int r = 0; r < 4; r++) c[mf][nf][r] = 0.f;

    const int KT = K >> 5;

    auto load_stage = [&](int stage, int kt) {
        bf16* As = gsm + stage * STAGE_ELEMS;
        bf16* Bs = As + 128 * AS_STR;
        int k0 = kt << 5;
        #pragma unroll
        for (int r = 0; r < 2; r++) {
            int q = tid + r * 256;
            int arow = q >> 2, ac = q & 3;
            cp16(As + arow * AS_STR + ac * 8,
                 A + (long long)(m0 + arow) * K + k0 + ac * 8);
            int brow = q >> 4, bc = q & 15;
            cp16(Bs + brow * BS_STR + bc * 8,
                 B + (long long)(k0 + brow) * N + n0 + bc * 8);
        }
    };

    load_stage(0, 0);
    asm volatile("cp.async.commit_group;\n");
    load_stage(1, 1);
    asm volatile("cp.async.commit_group;\n");

    for (int kt = 0; kt < KT; kt++) {
        asm volatile("cp.async.wait_group 1;\n");
        __syncthreads();

        if (kt + 2 < KT) load_stage((kt + 2) % NSTAGE, kt + 2);
        asm volatile("cp.async.commit_group;\n");

        const bf16* As = gsm + (kt % NSTAGE) * STAGE_ELEMS;
        const bf16* Bs = As + 128 * AS_STR;

        #pragma unroll
        for (int ks = 0; ks < 2; ks++) {
            int kb = ks * 16;
            uint32_t a[4][4], b[4][2];
            #pragma unroll
            for (int mf = 0; mf < 4; mf++)
                ldm_x4(a[mf][0], a[mf][1], a[mf][2], a[mf][3],
                       As + (wm + mf * 16 + t1 * 8 + rr) * AS_STR + kb + t2 * 8);
            #pragma unroll
            for (int nh = 0; nh < 2; nh++) {
                uint32_t r0, r1, r2, r3;
                ldm_x4_t(r0, r1, r2, r3,
                         Bs + (kb + t1 * 8 + rr) * BS_STR + wn + nh * 16 + t2 * 8);
                b[nh * 2][0] = r0; b[nh * 2][1] = r1;
                b[nh * 2 + 1][0] = r2; b[nh * 2 + 1][1] = r3;
            }
            #pragma unroll
            for (int mf = 0; mf < 4; mf++)
                #pragma unroll
                for (int nf = 0; nf < 4; nf++)
                    mma_bf16(c[mf][nf], a[mf], b[nf]);
        }
    }

    float* Cf = (float*)Cv;
    bf16*  Cb = (bf16*)Cv;
    #pragma unroll
    for (int mf = 0; mf < 4; mf++) {
        int r0 = m0 + wm + mf * 16 + g;
        int r1 = r0 + 8;
        long long d0 = r0, d1 = r1;
        if (EPI == 1) { d0 = map_winrow_to_token(r0); d1 = map_winrow_to_token(r1); }
        #pragma unroll
        for (int nf = 0; nf < 4; nf++) {
            int col = n0 + wn + nf * 8 + tg * 2;
            float b0 = bias[col], b1 = bias[col + 1];
            #pragma unroll
            for (int half = 0; half < 2; half++) {
                long long row = half ? r1 : r0;
                long long dst = half ? d1 : d0;
                float v0 = c[mf][nf][half * 2 + 0] + b0;
                float v1 = c[mf][nf][half * 2 + 1] + b1;
                if (ACT == 1) {
                    v0 = 0.5f * v0 * (1.f + erff(v0 * 0.70710678118654752f));
                    v1 = 0.5f * v1 * (1.f + erff(v1 * 0.70710678118654752f));
                }
                if (EPI == 1) {
                    float2 rv = *(const float2*)(res + dst * 128 + col);
                    *(float2*)(Cf + dst * 128 + col) = make_float2(rv.x + v0, rv.y + v1);
                } else if (EPI == 2) {
                    float2 rv = *(const float2*)(res + row * N + col);
                    *(float2*)(Cf + row * N + col) = make_float2(rv.x + v0, rv.y + v1);
                } else if (OUTBF) {
                    *(bf162*)(Cb + row * N + col) = __floats2bfloat162_rn(v0, v1);
                } else {
                    *(float2*)(Cf + row * N + col) = make_float2(v0, v1);
                }
            }
        }
    }
}

// ---------------------------------------------------------------------------
// launch
// ---------------------------------------------------------------------------
extern "C" void kernel_launch(void* const* d_in, const int* in_sizes, int n_in,
                              void* d_out, int out_size)
{
    const float* x       = (const float*)d_in[0];
    const float* norm1_g = (const float*)d_in[1];
    const float* norm1_b = (const float*)d_in[2];
    const float* qkv_w   = (const float*)d_in[3];
    const float* qkv_b   = (const float*)d_in[4];
    const float* rpb     = (const float*)d_in[5];
    const float* proj_w  = (const float*)d_in[6];
    const float* proj_b  = (const float*)d_in[7];
    const float* norm2_g = (const float*)d_in[8];
    const float* norm2_b = (const float*)d_in[9];
    const float* fc1_w   = (const float*)d_in[10];
    const float* fc1_b   = (const float*)d_in[11];
    const float* fc2_w   = (const float*)d_in[12];
    const float* fc2_b   = (const float*)d_in[13];
    float* out = (float*)d_out;

    bf16 *xw, *qkv, *att, *h2, *hid, *wqkv, *wproj, *wfc1, *wfc2;
    float *x1;
    cudaGetSymbolAddress((void**)&xw,   g_xw);
    cudaGetSymbolAddress((void**)&qkv,  g_qkv);
    cudaGetSymbolAddress((void**)&att,  g_att);
    cudaGetSymbolAddress((void**)&x1,   g_x1);
    cudaGetSymbolAddress((void**)&h2,   g_h2);
    cudaGetSymbolAddress((void**)&hid,  g_hid);
    cudaGetSymbolAddress((void**)&wqkv, g_wqkv);
    cudaGetSymbolAddress((void**)&wproj,g_wproj);
    cudaGetSymbolAddress((void**)&wfc1, g_wfc1);
    cudaGetSymbolAddress((void**)&wfc2, g_wfc2);

    cudaFuncSetAttribute(attn2_kernel, cudaFuncAttributeMaxDynamicSharedMemorySize, ATT2_SMEM);
    cudaFuncSetAttribute(gemm_bf<0,0,1>, cudaFuncAttributeMaxDynamicSharedMemorySize, GEMM_SMEM);
    cudaFuncSetAttribute(gemm_bf<0,1,0>, cudaFuncAttributeMaxDynamicSharedMemorySize, GEMM_SMEM);
    cudaFuncSetAttribute(gemm_bf<1,0,1>, cudaFuncAttributeMaxDynamicSharedMemorySize, GEMM_SMEM);
    cudaFuncSetAttribute(gemm_bf<0,2,0>, cudaFuncAttributeMaxDynamicSharedMemorySize, GEMM_SMEM);

    // 0) weight conversion
    f2bf_kernel<<<(128 * 384 + 255) / 256, 256>>>(qkv_w,  wqkv,  128 * 384);
    f2bf_kernel<<<(128 * 128 + 255) / 256, 256>>>(proj_w, wproj, 128 * 128);
    f2bf_kernel<<<(128 * 512 + 255) / 256, 256>>>(fc1_w,  wfc1,  128 * 512);
    f2bf_kernel<<<(512 * 128 + 255) / 256, 256>>>(fc2_w,  wfc2,  512 * 128);

    // 1) LN1 + shift + window partition -> bf16
    ln_kernel<<<Bn_TOK, 128>>>(x, norm1_g, norm1_b, xw, 1);

    // 2) QKV projection -> bf16
    gemm_bf<0, 0, 1><<<dim3(3, Bn_TOK / 128), 256, GEMM_SMEM>>>(
        xw, wqkv, qkv_b, qkv, nullptr, Bn_TOK, 384, 128);

    // 3) windowed attention (tensor cores) -> bf16
    attn2_kernel<<<NWIN * 4, 256, ATT2_SMEM>>>(qkv, rpb, att);

    // 4) proj + window reverse + unshift + residual -> fp32 x1
    gemm_bf<0, 1, 0><<<dim3(1, Bn_TOK / 128), 256, GEMM_SMEM>>>(
        att, wproj, proj_b, x1, x, Bn_TOK, 128, 128);

    // 5) LN2 -> bf16
    ln_kernel<<<Bn_TOK, 128>>>(x1, norm2_g, norm2_b, h2, 0);

    // 6) fc1 + GELU -> bf16
    gemm_bf<1, 0, 1><<<dim3(4, Bn_TOK / 128), 256, GEMM_SMEM>>>(
        h2, wfc1, fc1_b, hid, nullptr, Bn_TOK, 512, 128);

    // 7) fc2 + residual -> fp32 out
    gemm_bf<0, 2, 0><<<dim3(1, Bn_TOK / 128), 256, GEMM_SMEM>>>(
        hid, wfc2, fc2_b, out, x1, Bn_TOK, 128, 512);
}

// round 11
// speedup vs baseline: 7.7112x; 1.4071x over previous
#include <cuda_runtime.h>
#include <cuda_bf16.h>
#include <math.h>
#include <stdint.h>

typedef __nv_bfloat16  bf16;
typedef __nv_bfloat162 bf162;

#define Bn_TOK   100352      // 8*4*56*56 = 1024 windows * 98
#define NWIN     1024
#define SCALE_Q  0.17677669529663687f   // 32^-0.5
#define LN_EPS   1e-5f

// ---------------------------------------------------------------------------
// Scratch
// ---------------------------------------------------------------------------
__device__ bf16  g_xw  [(long long)Bn_TOK * 128];
__device__ bf16  g_qkv [(long long)Bn_TOK * 384];
__device__ bf16  g_att [(long long)Bn_TOK * 128];
__device__ float g_x1  [(long long)Bn_TOK * 128];
__device__ bf16  g_h2  [(long long)Bn_TOK * 128];
__device__ bf16  g_hid [(long long)Bn_TOK * 512];
__device__ bf16  g_wqkv[128 * 384];
__device__ bf16  g_wproj[128 * 128];
__device__ bf16  g_wfc1[128 * 512];
__device__ bf16  g_wfc2[512 * 128];

// ---------------------------------------------------------------------------
__global__ void f2bf_kernel(const float* __restrict__ s, bf16* __restrict__ d, int n)
{
    int i = blockIdx.x * 256 + threadIdx.x;
    if (i < n) d[i] = __float2bfloat16(s[i]);
}

__device__ __forceinline__ int map_winrow_to_token(int row)
{
    int win = row / 98, n = row - win * 98;
    int b    = win >> 7;
    int winS = win & 127;
    int wd = winS >> 6, wh = (winS >> 3) & 7, ww = winS & 7;
    int td = n / 49, rem = n - td * 49, th = rem / 7, tw = rem - th * 7;
    int d = wd * 2 + td;
    int h = wh * 7 + th;
    int w = ww * 7 + tw;
    int ds = (d + 1) & 3;
    int hs = h + 3; if (hs >= 56) hs -= 56;
    int ws = w + 3; if (ws >= 56) ws -= 56;
    return ((b * 4 + ds) * 56 + hs) * 56 + ws;
}

// ---------------------------------------------------------------------------
// LayerNorm: warp per token, 8 tokens per 256-thread block.
// ---------------------------------------------------------------------------
__global__ void __launch_bounds__(256)
ln_kernel(const float* __restrict__ in,
          const float* __restrict__ gam,
          const float* __restrict__ bet,
          bf16* __restrict__ out, int gather)
{
    int warp = threadIdx.x >> 5, lane = threadIdx.x & 31;
    int row  = blockIdx.x * 8 + warp;
    int src  = gather ? map_winrow_to_token(row) : row;

    float4 v = ((const float4*)(in + (long long)src * 128))[lane];
    float s  = v.x + v.y + v.z + v.w;
    float s2 = v.x * v.x + v.y * v.y + v.z * v.z + v.w * v.w;
    #pragma unroll
    for (int o = 16; o; o >>= 1) {
        s  += __shfl_xor_sync(0xffffffffu, s,  o);
        s2 += __shfl_xor_sync(0xffffffffu, s2, o);
    }
    float mu = s * (1.f / 128.f);
    float rs = rsqrtf(s2 * (1.f / 128.f) - mu * mu + LN_EPS);

    float4 gv = ((const float4*)gam)[lane];
    float4 bv = ((const float4*)bet)[lane];
    float o0 = (v.x - mu) * rs * gv.x + bv.x;
    float o1 = (v.y - mu) * rs * gv.y + bv.y;
    float o2 = (v.z - mu) * rs * gv.z + bv.z;
    float o3 = (v.w - mu) * rs * gv.w + bv.w;
    bf162* po = (bf162*)(out + (long long)row * 128 + lane * 4);
    po[0] = __floats2bfloat162_rn(o0, o1);
    po[1] = __floats2bfloat162_rn(o2, o3);
}

// ---------------------------------------------------------------------------
// MMA primitives
// ---------------------------------------------------------------------------
__device__ __forceinline__ void cp16(void* dst, const void* src)
{
    uint32_t d = (uint32_t)__cvta_generic_to_shared(dst);
    asm volatile("cp.async.ca.shared.global [%0], [%1], 16;\n" :: "r"(d), "l"(src));
}
__device__ __forceinline__ void ldm_x4(uint32_t& r0, uint32_t& r1, uint32_t& r2,
                                       uint32_t& r3, const bf16* p)
{
    uint32_t a = (uint32_t)__cvta_generic_to_shared(p);
    asm volatile("ldmatrix.sync.aligned.m8n8.x4.shared.b16 {%0,%1,%2,%3}, [%4];\n"
                 : "=r"(r0), "=r"(r1), "=r"(r2), "=r"(r3) : "r"(a));
}
__device__ __forceinline__ void ldm_x4_t(uint32_t& r0, uint32_t& r1, uint32_t& r2,
                                         uint32_t& r3, const bf16* p)
{
    uint32_t a = (uint32_t)__cvta_generic_to_shared(p);
    asm volatile("ldmatrix.sync.aligned.m8n8.x4.trans.shared.b16 {%0,%1,%2,%3}, [%4];\n"
                 : "=r"(r0), "=r"(r1), "=r"(r2), "=r"(r3) : "r"(a));
}
__device__ __forceinline__ void mma_bf16(float c[4], const uint32_t a[4], const uint32_t b[2])
{
    asm volatile(
        "mma.sync.aligned.m16n8k16.row.col.f32.bf16.bf16.f32 "
        "{%0,%1,%2,%3}, {%4,%5,%6,%7}, {%8,%9}, {%0,%1,%2,%3};\n"
        : "+f"(c[0]), "+f"(c[1]), "+f"(c[2]), "+f"(c[3])
        : "r"(a[0]), "r"(a[1]), "r"(a[2]), "r"(a[3]), "r"(b[0]), "r"(b[1]));
}

// ---------------------------------------------------------------------------
// Tensor-core windowed attention, in-register softmax (branch-free shuffles).
// One block per (window, head), 256 threads (8 warps).
// smem: q_s[128][40] | k_s[112][40] | v_s[112][40] | P[128][120] | rpb[507] | jd[112]
// ---------------------------------------------------------------------------
#define ATT2_SMEM 61376

__global__ void __launch_bounds__(256)
attn2_kernel(const bf16* __restrict__ qkv,
             const float* __restrict__ rpb,
             bf16* __restrict__ out)
{
    extern __shared__ char smc[];
    bf16*  q_s   = (bf16*)(smc);
    bf16*  k_s   = (bf16*)(smc + 10240);
    bf16*  v_s   = (bf16*)(smc + 19200);
    bf16*  P     = (bf16*)(smc + 28160);
    float* rpb_s = (float*)(smc + 58880);
    int*   jd    = (int*)  (smc + 60908);

    int blk  = blockIdx.x;
    int win  = blk >> 2;
    int head = blk & 3;
    int tid  = threadIdx.x;
    int w    = tid >> 5, lane = tid & 31;
    int g    = lane >> 2, tg = lane & 3;
    int t1   = (lane >> 3) & 1;
    int t2   = lane >> 4;
    int rr   = lane & 7;
    int m0   = w * 16;

    int winS = win & 127;
    int wd = winS >> 6, wh = (winS >> 3) & 7, ww = winS & 7;
    if (tid < 112) {
        int v = 0;
        if (tid < 98) {
            int td = tid / 49, rem = tid - td * 49, th = rem / 7, tw = rem - th * 7;
            int d = wd * 2 + td, h = wh * 7 + th, wq = ww * 7 + tw;
            int dr = d < 2 ? 0 : (d < 3 ? 1 : 2);
            int hr = h < 49 ? 0 : (h < 53 ? 1 : 2);
            int wr = wq < 49 ? 0 : (wq < 53 ? 1 : 2);
            v = td | (th << 4) | (tw << 8) | ((dr * 9 + hr * 3 + wr) << 12);
        }
        jd[tid] = v;
    }
    for (int i = tid; i < 507; i += 256) rpb_s[i] = rpb[i * 4 + head];

    const bf16* base = qkv + (long long)win * 98 * 384 + head * 32;
    for (int idx = tid; idx < 98 * 4; idx += 256) {
        int row = idx >> 2, ch = idx & 3;
        const int4* src = (const int4*)(base + row * 384 + ch * 8);
        *(int4*)(q_s + row * 40 + ch * 8) = src[0];
        *(int4*)(k_s + row * 40 + ch * 8) = src[16];
        *(int4*)(v_s + row * 40 + ch * 8) = src[32];
    }
    int4 zz = make_int4(0, 0, 0, 0);
    for (int idx = tid; idx < 14 * 5; idx += 256) {
        int row = 98 + idx / 5, ch = idx % 5;
        *(int4*)(k_s + row * 40 + ch * 8) = zz;
        *(int4*)(v_s + row * 40 + ch * 8) = zz;
    }
    __syncthreads();

    // ---- S = q @ k^T ----
    float c[14][4];
    #pragma unroll
    for (int nt = 0; nt < 14; nt++)
        #pragma unroll
        for (int e = 0; e < 4; e++) c[nt][e] = 0.f;

    #pragma unroll
    for (int kh = 0; kh < 2; kh++) {
        int kb = kh * 16;
        uint32_t a[4];
        ldm_x4(a[0], a[1], a[2], a[3], q_s + (m0 + t1 * 8 + rr) * 40 + kb + t2 * 8);
        #pragma unroll
        for (int np = 0; np < 7; np++) {
            uint32_t r0, r1, r2, r3;
            ldm_x4(r0, r1, r2, r3, k_s + (np * 16 + t1 * 8 + rr) * 40 + kb + t2 * 8);
            uint32_t b0[2] = {r0, r2};
            uint32_t b1[2] = {r1, r3};
            mma_bf16(c[np * 2],     a, b0);
            mma_bf16(c[np * 2 + 1], a, b1);
        }
    }

    // ---- scale + bias + mask + quad softmax (ALL lanes run the shuffles) ----
    #pragma unroll
    for (int half = 0; half < 2; half++) {
        int  i     = m0 + g + half * 8;
        bool valid = (i < 98);
        int  pi    = jd[valid ? i : 0];
        int  di = pi & 15, hi = (pi >> 4) & 15, wi = (pi >> 8) & 15, li = pi >> 12;

        float mx = -1e30f;
        #pragma unroll
        for (int nt = 0; nt < 14; nt++) {
            #pragma unroll
            for (int e = 0; e < 2; e++) {
                int j = nt * 8 + tg * 2 + e;
                float v = -1e30f;
                if (valid && j < 98) {
                    int pj = jd[j];
                    int dj = pj & 15, hj = (pj >> 4) & 15, wj = (pj >> 8) & 15;
                    int rel = (di - dj + 1) * 169 + (hi - hj + 6) * 13 + (wi - wj + 6);
                    float msk = (li == (pj >> 12)) ? 0.f : -100.f;
                    v = c[nt][half * 2 + e] * SCALE_Q + rpb_s[rel] + msk;
                }
                c[nt][half * 2 + e] = v;
                mx = fmaxf(mx, v);
            }
        }
        // quad reductions — executed unconditionally by every lane
        mx = fmaxf(mx, __shfl_xor_sync(0xffffffffu, mx, 1));
        mx = fmaxf(mx, __shfl_xor_sync(0xffffffffu, mx, 2));
        float sum = 0.f;
        #pragma unroll
        for (int nt = 0; nt < 14; nt++) {
            #pragma unroll
            for (int e = 0; e < 2; e++) {
                float ev = __expf(c[nt][half * 2 + e] - mx);
                c[nt][half * 2 + e] = ev;
                sum += ev;
            }
        }
        sum += __shfl_xor_sync(0xffffffffu, sum, 1);
        sum += __shfl_xor_sync(0xffffffffu, sum, 2);
        float inv = 1.f / sum;
        // write P (zeros for padded rows) — every lane writes its pair
        #pragma unroll
        for (int nt = 0; nt < 14; nt++) {
            float p0 = valid ? c[nt][half * 2]     * inv : 0.f;
            float p1 = valid ? c[nt][half * 2 + 1] * inv : 0.f;
            *(bf162*)(P + i * 120 + nt * 8 + tg * 2) = __floats2bfloat162_rn(p0, p1);
        }
    }
    __syncthreads();

    // ---- out = P @ v ----
    float c2[4][4];
    #pragma unroll
    for (int nt = 0; nt < 4; nt++)
        #pragma unroll
        for (int e = 0; e < 4; e++) c2[nt][e] = 0.f;

    #pragma unroll
    for (int kh = 0; kh < 7; kh++) {
        int kb = kh * 16;
        uint32_t a[4];
        ldm_x4(a[0], a[1], a[2], a[3], P + (m0 + t1 * 8 + rr) * 120 + kb + t2 * 8);
        #pragma unroll
        for (int ch = 0; ch < 2; ch++) {
            uint32_t r0, r1, r2, r3;
            ldm_x4_t(r0, r1, r2, r3, v_s + (kb + t1 * 8 + rr) * 40 + ch * 16 + t2 * 8);
            uint32_t b0[2] = {r0, r1};
            uint32_t b1[2] = {r2, r3};
            mma_bf16(c2[ch * 2],     a, b0);
            mma_bf16(c2[ch * 2 + 1], a, b1);
        }
    }

    bf16* obase = out + (long long)win * 98 * 128 + head * 32;
    #pragma unroll
    for (int half = 0; half < 2; half++) {
        int i = m0 + g + half * 8;
        if (i < 98) {
            #pragma unroll
            for (int nt = 0; nt < 4; nt++) {
                int col = nt * 8 + tg * 2;
                *(bf162*)(obase + (long long)i * 128 + col) =
                    __floats2bfloat162_rn(c2[nt][half * 2], c2[nt][half * 2 + 1]);
            }
        }
    }
}

// ---------------------------------------------------------------------------
// bf16 GEMM: BK=64, 2-stage cp.async pipeline. BM=BN=128, 256 threads.
// ---------------------------------------------------------------------------
#define AS_STR 72     // 64 + 8 pad
#define BS_STR 136    // 128 + 8 pad
#define STAGE_ELEMS (128 * AS_STR + 64 * BS_STR)   // 17920 bf16
#define GEMM_SMEM (2 * STAGE_ELEMS * 2)            // 71680 B

template<int ACT, int EPI, int OUTBF>
__global__ void __launch_bounds__(256, 2)
gemm_bf(const bf16* __restrict__ A, const bf16* __restrict__ B,
        const float* __restrict__ bias, void* __restrict__ Cv,
        const float* __restrict__ res, int M, int N, int K)
{
    extern __shared__ bf16 gsm[];
    int tid = threadIdx.x;
    int m0 = blockIdx.y * 128;
    int n0 = blockIdx.x * 128;

    int w    = tid >> 5, lane = tid & 31;
    int g    = lane >> 2, tg = lane & 3;
    int wm   = (w & 1) * 64;
    int wn   = (w >> 1) * 32;
    int t1   = (lane >> 3) & 1;
    int t2   = (lane >> 4);
    int rr   = lane & 7;

    float c[4][4][4];
    #pragma unroll
    for (int mf = 0; mf < 4; mf++)
        #pragma unroll
        for (int nf = 0; nf < 4; nf++)
            #pragma unroll
            for (int r = 0; r < 4; r++) c[mf][nf][r] = 0.f;

    const int KT = K >> 6;

    auto load_stage = [&](int stage, int kt) {
        bf16* As = gsm + stage * STAGE_ELEMS;
        bf16* Bs = As + 128 * AS_STR;
        int k0 = kt << 6;
        #pragma unroll
        for (int r = 0; r < 4; r++) {
            int q = tid + r * 256;
            int arow = q >> 3, ac = q & 7;             // 128 rows x 8 chunks
            cp16(As + arow * AS_STR + ac * 8,
                 A + (long long)(m0 + arow) * K + k0 + ac * 8);
            int brow = q >> 4, bc = q & 15;            // 64 rows x 16 chunks
            cp16(Bs + brow * BS_STR + bc * 8,
                 B + (long long)(k0 + brow) * N + n0 + bc * 8);
        }
    };

    load_stage(0, 0);
    asm volatile("cp.async.commit_group;\n");

    for (int kt = 0; kt < KT; kt++) {
        if (kt + 1 < KT) load_stage((kt + 1) & 1, kt + 1);
        asm volatile("cp.async.commit_group;\n");
        asm volatile("cp.async.wait_group 1;\n");
        __syncthreads();

        const bf16* As = gsm + (kt & 1) * STAGE_ELEMS;
        const bf16* Bs = As + 128 * AS_STR;

        #pragma unroll
        for (int ks = 0; ks < 4; ks++) {
            int kb = ks * 16;
            uint32_t a[4][4], b[4][2];
            #pragma unroll
            for (int mf = 0; mf < 4; mf++)
                ldm_x4(a[mf][0], a[mf][1], a[mf][2], a[mf][3],
                       As + (wm + mf * 16 + t1 * 8 + rr) * AS_STR + kb + t2 * 8);
            #pragma unroll
            for (int nh = 0; nh < 2; nh++) {
                uint32_t r0, r1, r2, r3;
                ldm_x4_t(r0, r1, r2, r3,
                         Bs + (kb + t1 * 8 + rr) * BS_STR + wn + nh * 16 + t2 * 8);
                b[nh * 2][0] = r0; b[nh * 2][1] = r1;
                b[nh * 2 + 1][0] = r2; b[nh * 2 + 1][1] = r3;
            }
            #pragma unroll
            for (int mf = 0; mf < 4; mf++)
                #pragma unroll
                for (int nf = 0; nf < 4; nf++)
                    mma_bf16(c[mf][nf], a[mf], b[nf]);
        }
        __syncthreads();
    }

    float* Cf = (float*)Cv;
    bf16*  Cb = (bf16*)Cv;
    #pragma unroll
    for (int mf = 0; mf < 4; mf++) {
        int r0 = m0 + wm + mf * 16 + g;
        int r1 = r0 + 8;
        long long d0 = r0, d1 = r1;
        if (EPI == 1) { d0 = map_winrow_to_token(r0); d1 = map_winrow_to_token(r1); }
        #pragma unroll
        for (int nf = 0; nf < 4; nf++) {
            int col = n0 + wn + nf * 8 + tg * 2;
            float b0 = bias[col], b1 = bias[col + 1];
            #pragma unroll
            for (int half = 0; half < 2; half++) {
                long long row = half ? r1 : r0;
                long long dst = half ? d1 : d0;
                float v0 = c[mf][nf][half * 2 + 0] + b0;
                float v1 = c[mf][nf][half * 2 + 1] + b1;
                if (ACT == 1) {
                    v0 = 0.5f * v0 * (1.f + erff(v0 * 0.70710678118654752f));
                    v1 = 0.5f * v1 * (1.f + erff(v1 * 0.70710678118654752f));
                }
                if (EPI == 1) {
                    float2 rv = *(const float2*)(res + dst * 128 + col);
                    *(float2*)(Cf + dst * 128 + col) = make_float2(rv.x + v0, rv.y + v1);
                } else if (EPI == 2) {
                    float2 rv = *(const float2*)(res + row * N + col);
                    *(float2*)(Cf + row * N + col) = make_float2(rv.x + v0, rv.y + v1);
                } else if (OUTBF) {
                    *(bf162*)(Cb + row * N + col) = __floats2bfloat162_rn(v0, v1);
                } else {
                    *(float2*)(Cf + row * N + col) = make_float2(v0, v1);
                }
            }
        }
    }
}

// ---------------------------------------------------------------------------
// launch
// ---------------------------------------------------------------------------
extern "C" void kernel_launch(void* const* d_in, const int* in_sizes, int n_in,
                              void* d_out, int out_size)
{
    const float* x       = (const float*)d_in[0];
    const float* norm1_g = (const float*)d_in[1];
    const float* norm1_b = (const float*)d_in[2];
    const float* qkv_w   = (const float*)d_in[3];
    const float* qkv_b   = (const float*)d_in[4];
    const float* rpb     = (const float*)d_in[5];
    const float* proj_w  = (const float*)d_in[6];
    const float* proj_b  = (const float*)d_in[7];
    const float* norm2_g = (const float*)d_in[8];
    const float* norm2_b = (const float*)d_in[9];
    const float* fc1_w   = (const float*)d_in[10];
    const float* fc1_b   = (const float*)d_in[11];
    const float* fc2_w   = (const float*)d_in[12];
    const float* fc2_b   = (const float*)d_in[13];
    float* out = (float*)d_out;

    bf16 *xw, *qkv, *att, *h2, *hid, *wqkv, *wproj, *wfc1, *wfc2;
    float *x1;
    cudaGetSymbolAddress((void**)&xw,   g_xw);
    cudaGetSymbolAddress((void**)&qkv,  g_qkv);
    cudaGetSymbolAddress((void**)&att,  g_att);
    cudaGetSymbolAddress((void**)&x1,   g_x1);
    cudaGetSymbolAddress((void**)&h2,   g_h2);
    cudaGetSymbolAddress((void**)&hid,  g_hid);
    cudaGetSymbolAddress((void**)&wqkv, g_wqkv);
    cudaGetSymbolAddress((void**)&wproj,g_wproj);
    cudaGetSymbolAddress((void**)&wfc1, g_wfc1);
    cudaGetSymbolAddress((void**)&wfc2, g_wfc2);

    cudaFuncSetAttribute(attn2_kernel, cudaFuncAttributeMaxDynamicSharedMemorySize, ATT2_SMEM);
    cudaFuncSetAttribute(gemm_bf<0,0,1>, cudaFuncAttributeMaxDynamicSharedMemorySize, GEMM_SMEM);
    cudaFuncSetAttribute(gemm_bf<0,1,0>, cudaFuncAttributeMaxDynamicSharedMemorySize, GEMM_SMEM);
    cudaFuncSetAttribute(gemm_bf<1,0,1>, cudaFuncAttributeMaxDynamicSharedMemorySize, GEMM_SMEM);
    cudaFuncSetAttribute(gemm_bf<0,2,0>, cudaFuncAttributeMaxDynamicSharedMemorySize, GEMM_SMEM);

    // 0) weight conversion
    f2bf_kernel<<<(128 * 384 + 255) / 256, 256>>>(qkv_w,  wqkv,  128 * 384);
    f2bf_kernel<<<(128 * 128 + 255) / 256, 256>>>(proj_w, wproj, 128 * 128);
    f2bf_kernel<<<(128 * 512 + 255) / 256, 256>>>(fc1_w,  wfc1,  128 * 512);
    f2bf_kernel<<<(512 * 128 + 255) / 256, 256>>>(fc2_w,  wfc2,  512 * 128);

    // 1) LN1 + shift + window partition -> bf16
    ln_kernel<<<Bn_TOK / 8, 256>>>(x, norm1_g, norm1_b, xw, 1);

    // 2) QKV projection -> bf16
    gemm_bf<0, 0, 1><<<dim3(3, Bn_TOK / 128), 256, GEMM_SMEM>>>(
        xw, wqkv, qkv_b, qkv, nullptr, Bn_TOK, 384, 128);

    // 3) windowed attention (tensor cores, in-register softmax) -> bf16
    attn2_kernel<<<NWIN * 4, 256, ATT2_SMEM>>>(qkv, rpb, att);

    // 4) proj + window reverse + unshift + residual -> fp32 x1
    gemm_bf<0, 1, 0><<<dim3(1, Bn_TOK / 128), 256, GEMM_SMEM>>>(
        att, wproj, proj_b, x1, x, Bn_TOK, 128, 128);

    // 5) LN2 -> bf16
    ln_kernel<<<Bn_TOK / 8, 256>>>(x1, norm2_g, norm2_b, h2, 0);

    // 6) fc1 + GELU -> bf16
    gemm_bf<1, 0, 1><<<dim3(4, Bn_TOK / 128), 256, GEMM_SMEM>>>(
        h2, wfc1, fc1_b, hid, nullptr, Bn_TOK, 512, 128);

    // 7) fc2 + residual -> fp32 out
    gemm_bf<0, 2, 0><<<dim3(1, Bn_TOK / 128), 256, GEMM_SMEM>>>(
        hid, wfc2, fc2_b, out, x1, Bn_TOK, 128, 512);
}